// round 9
// baseline (speedup 1.0000x reference)
#include <cuda_runtime.h>

#define HID 64
#define G3  192

typedef unsigned long long ull;

// scratch for h0 between the two kernels (B=131072 rows x 64)
__device__ float g_h0[131072ull * 64];

__device__ __forceinline__ void fma2(ull& d, ull a, ull b) {
    asm("fma.rn.f32x2 %0, %1, %2, %0;" : "+l"(d) : "l"(a), "l"(b));
}
__device__ __forceinline__ float2 unpack2(ull v) {
    float2 f; asm("mov.b64 {%0, %1}, %2;" : "=f"(f.x), "=f"(f.y) : "l"(v)); return f;
}
__device__ __forceinline__ float sigf(float v)  { return 1.0f / (1.0f + __expf(-v)); }
__device__ __forceinline__ float tanhfast(float v) {
    return 1.0f - 2.0f / (__expf(2.0f * v) + 1.0f);
}

// ============================================================================
// K1: h0 = token @ whw^T + whb      [B,1024] x [64,1024]^T -> [B,64]
// 128 rows/block, 8 warps, 16 rows/warp; lane owns m-pair (2*lan, 2*lan+1)
// via k-parity f32x2 accumulation. Register-prefetch double buffering.
// ============================================================================
#define K1_TOK   0                 // 128*68 = 8704
#define K1_W1    8704              // 32*132 = 4224 (k-pair interleaved)
#define K1_SMEMF (8704 + 4224)     // 12928 floats
#define K1_SMEMB (K1_SMEMF * 4)    // 51712 B

__global__ void __launch_bounds__(256, 2)
head_gemm(const float* __restrict__ token,
          const float* __restrict__ whw,
          const float* __restrict__ whb,
          int B, int NE)
{
    extern __shared__ float sm[];
    const int tid  = threadIdx.x;
    const int wid  = tid >> 5;
    const int lan  = tid & 31;
    const int m0   = 2 * lan;
    const int row0 = blockIdx.x * 128;
    const int wrow = wid * 16;

    ull acc[16][2];
#pragma unroll
    for (int r = 0; r < 16; r++) { acc[r][0] = 0ull; acc[r][1] = 0ull; }

    const int nch = NE >> 6;

    float4 tpf[8], wpf[4];
    // prefetch chunk 0
#pragma unroll
    for (int ii = 0; ii < 8; ii++) {
        int i = tid + ii * 256;
        int r = i >> 4, c4 = i & 15;
        int gr = row0 + r;
        tpf[ii] = make_float4(0.f, 0.f, 0.f, 0.f);
        if (gr < B)
            tpf[ii] = reinterpret_cast<const float4*>(token)[(size_t)gr * (NE >> 2) + c4];
    }
#pragma unroll
    for (int ii = 0; ii < 4; ii++) {
        int i = tid + ii * 256;
        int m = i >> 4, k4 = i & 15;
        wpf[ii] = reinterpret_cast<const float4*>(whw)[(size_t)m * (NE >> 2) + k4];
    }

#pragma unroll 1
    for (int kc = 0; kc < nch; kc++) {
        __syncthreads();
        // commit prefetched tiles to smem
#pragma unroll
        for (int ii = 0; ii < 8; ii++) {
            int i = tid + ii * 256;
            int r = i >> 4, c4 = i & 15;
            *reinterpret_cast<float4*>(&sm[K1_TOK + r * 68 + c4 * 4]) = tpf[ii];
        }
#pragma unroll
        for (int ii = 0; ii < 4; ii++) {
            int i = tid + ii * 256;
            int m = i >> 4, k4 = i & 15;
            float4 v = wpf[ii];
            sm[K1_W1 + (2 * k4 + 0) * 132 + 2 * m + 0] = v.x;
            sm[K1_W1 + (2 * k4 + 0) * 132 + 2 * m + 1] = v.y;
            sm[K1_W1 + (2 * k4 + 1) * 132 + 2 * m + 0] = v.z;
            sm[K1_W1 + (2 * k4 + 1) * 132 + 2 * m + 1] = v.w;
        }
        __syncthreads();
        // prefetch next chunk (overlaps with compute below)
        if (kc + 1 < nch) {
#pragma unroll
            for (int ii = 0; ii < 8; ii++) {
                int i = tid + ii * 256;
                int r = i >> 4, c4 = i & 15;
                int gr = row0 + r;
                tpf[ii] = make_float4(0.f, 0.f, 0.f, 0.f);
                if (gr < B)
                    tpf[ii] = reinterpret_cast<const float4*>(token)
                                  [(size_t)gr * (NE >> 2) + (kc + 1) * 16 + c4];
            }
#pragma unroll
            for (int ii = 0; ii < 4; ii++) {
                int i = tid + ii * 256;
                int m = i >> 4, k4 = i & 15;
                wpf[ii] = reinterpret_cast<const float4*>(whw)
                              [(size_t)m * (NE >> 2) + (kc + 1) * 16 + k4];
            }
        }
        // compute
#pragma unroll
        for (int k2e = 0; k2e < 32; k2e += 2) {
            ulonglong2 wv0 = *reinterpret_cast<const ulonglong2*>(&sm[K1_W1 + k2e * 132 + 4 * lan]);
            ulonglong2 wv1 = *reinterpret_cast<const ulonglong2*>(&sm[K1_W1 + (k2e + 1) * 132 + 4 * lan]);
#pragma unroll
            for (int r = 0; r < 16; r++) {
                ulonglong2 tp = *reinterpret_cast<const ulonglong2*>(
                    &sm[K1_TOK + (wrow + r) * 68 + k2e * 2]);
                fma2(acc[r][0], tp.x, wv0.x);
                fma2(acc[r][1], tp.x, wv0.y);
                fma2(acc[r][0], tp.y, wv1.x);
                fma2(acc[r][1], tp.y, wv1.y);
            }
        }
    }

    float b0 = whb[m0], b1 = whb[m0 + 1];
#pragma unroll
    for (int r = 0; r < 16; r++) {
        int gr = row0 + wrow + r;
        if (gr < B) {
            float2 a0 = unpack2(acc[r][0]);
            float2 a1 = unpack2(acc[r][1]);
            *reinterpret_cast<float2*>(&g_h0[(size_t)gr * 64 + m0])
                = make_float2(a0.x + a0.y + b0, a1.x + a1.y + b1);
        }
    }
}

// ============================================================================
// K2: GRU recurrence. 64 rows/block, 8 warps, 8 rows/warp; lane owns m-pair.
// h kept in smem DUPLICATED (hbd[2k]=hbd[2k+1]=h[k]) so the f32x2 h-operand
// comes straight from LDS.128 broadcast — no pack movs in the hot loop.
// Rows are warp-private -> single in-place h buffer, no block barriers.
// ============================================================================
#define K2_WHH  0                  // [k][192]  12288
#define K2_WIH0 12288              // 192
#define K2_WIH1 (12288+192)
#define K2_BIH  (12288+384)
#define K2_BHH  (12288+576)
#define K2_WO0  (12288+768)        // 64
#define K2_WO1  (12288+832)
#define K2_OUTB (12288+896)        // 2
#define K2_HBD  13188              // 64*128 = 8192 (duplicated h)
#define K2_SMEMF (13188 + 8192)    // 21380 floats
#define K2_SMEMB (K2_SMEMF * 4)    // 85520 B

__global__ void __launch_bounds__(256, 2)
gru_steps(const float* __restrict__ wih,   // [192, 2]
          const float* __restrict__ whhg,  // [192, 64]
          const float* __restrict__ bihg,  // [192]
          const float* __restrict__ bhhg,  // [192]
          const float* __restrict__ wow,   // [2, 64]
          const float* __restrict__ wob,   // [2]
          float* __restrict__ out,         // [B, T, 2]
          int B, int T)
{
    extern __shared__ float sm[];
    const int tid  = threadIdx.x;
    const int wid  = tid >> 5;
    const int lan  = tid & 31;
    const int m0   = 2 * lan;
    const int row0 = blockIdx.x * 64;
    const int wrow = wid * 8;

    // stage w_hh transposed [k][j]
    for (int idx = tid; idx < G3 * (HID / 4); idx += 256) {
        int j  = idx >> 4;
        int k4 = idx & 15;
        float4 v = reinterpret_cast<const float4*>(whhg)[j * (HID / 4) + k4];
        sm[K2_WHH + (k4 * 4 + 0) * G3 + j] = v.x;
        sm[K2_WHH + (k4 * 4 + 1) * G3 + j] = v.y;
        sm[K2_WHH + (k4 * 4 + 2) * G3 + j] = v.z;
        sm[K2_WHH + (k4 * 4 + 3) * G3 + j] = v.w;
    }
    for (int j = tid; j < G3; j += 256) {
        sm[K2_WIH0 + j] = wih[j * 2 + 0];
        sm[K2_WIH1 + j] = wih[j * 2 + 1];
        sm[K2_BIH + j]  = bihg[j];
        sm[K2_BHH + j]  = bhhg[j];
    }
    if (tid < HID) {
        sm[K2_WO0 + tid] = wow[tid];
        sm[K2_WO1 + tid] = wow[HID + tid];
    }
    if (tid < 2) sm[K2_OUTB + tid] = wob[tid];

    // stage h0 (duplicated): hbd[r][2k] = hbd[r][2k+1] = h0[row][k]
    for (int i = tid; i < 64 * 16; i += 256) {
        int r  = i >> 4;
        int c4 = i & 15;
        int gr = row0 + r;
        float4 v = make_float4(0.f, 0.f, 0.f, 0.f);
        if (gr < B)
            v = reinterpret_cast<const float4*>(g_h0)[(size_t)gr * 16 + c4];
        *reinterpret_cast<float4*>(&sm[K2_HBD + r * 128 + c4 * 8])
            = make_float4(v.x, v.x, v.y, v.y);
        *reinterpret_cast<float4*>(&sm[K2_HBD + r * 128 + c4 * 8 + 4])
            = make_float4(v.z, v.z, v.w, v.w);
    }
    __syncthreads();

    float x0[8], x1[8];
#pragma unroll
    for (int r = 0; r < 8; r++) { x0[r] = 0.f; x1[r] = 0.f; }

#pragma unroll 1
    for (int step = 0; step < T; step++) {
        ull A[8][3];
#pragma unroll
        for (int r = 0; r < 8; r++) { A[r][0] = 0ull; A[r][1] = 0ull; A[r][2] = 0ull; }

#pragma unroll
        for (int k4 = 0; k4 < 16; k4++) {
            // weights for k = 4*k4 .. 4*k4+3, this lane's m-pair, 3 gates
            ull w[12];
#pragma unroll
            for (int c = 0; c < 4; c++) {
                const float* wk = &sm[K2_WHH + (k4 * 4 + c) * G3 + m0];
                w[c * 3 + 0] = *reinterpret_cast<const ull*>(wk);
                w[c * 3 + 1] = *reinterpret_cast<const ull*>(wk + 64);
                w[c * 3 + 2] = *reinterpret_cast<const ull*>(wk + 128);
            }
#pragma unroll
            for (int r = 0; r < 8; r++) {
                const float* hb = &sm[K2_HBD + (wrow + r) * 128 + k4 * 8];
                ulonglong2 ha = *reinterpret_cast<const ulonglong2*>(hb);      // {h0,h0},{h1,h1}
                ulonglong2 hq = *reinterpret_cast<const ulonglong2*>(hb + 4);  // {h2,h2},{h3,h3}
                fma2(A[r][0], ha.x, w[0]);  fma2(A[r][1], ha.x, w[1]);  fma2(A[r][2], ha.x, w[2]);
                fma2(A[r][0], ha.y, w[3]);  fma2(A[r][1], ha.y, w[4]);  fma2(A[r][2], ha.y, w[5]);
                fma2(A[r][0], hq.x, w[6]);  fma2(A[r][1], hq.x, w[7]);  fma2(A[r][2], hq.x, w[8]);
                fma2(A[r][0], hq.y, w[9]);  fma2(A[r][1], hq.y, w[10]); fma2(A[r][2], hq.y, w[11]);
            }
        }

        // gate math: lane-local for m0, m0+1
        float2 wi0r = *reinterpret_cast<const float2*>(&sm[K2_WIH0 + m0]);
        float2 wi0z = *reinterpret_cast<const float2*>(&sm[K2_WIH0 + 64 + m0]);
        float2 wi0n = *reinterpret_cast<const float2*>(&sm[K2_WIH0 + 128 + m0]);
        float2 wi1r = *reinterpret_cast<const float2*>(&sm[K2_WIH1 + m0]);
        float2 wi1z = *reinterpret_cast<const float2*>(&sm[K2_WIH1 + 64 + m0]);
        float2 wi1n = *reinterpret_cast<const float2*>(&sm[K2_WIH1 + 128 + m0]);
        float2 bir  = *reinterpret_cast<const float2*>(&sm[K2_BIH + m0]);
        float2 biz  = *reinterpret_cast<const float2*>(&sm[K2_BIH + 64 + m0]);
        float2 bin  = *reinterpret_cast<const float2*>(&sm[K2_BIH + 128 + m0]);
        float2 bhr  = *reinterpret_cast<const float2*>(&sm[K2_BHH + m0]);
        float2 bhz  = *reinterpret_cast<const float2*>(&sm[K2_BHH + 64 + m0]);
        float2 bhn  = *reinterpret_cast<const float2*>(&sm[K2_BHH + 128 + m0]);
        float2 wo0p = *reinterpret_cast<const float2*>(&sm[K2_WO0 + m0]);
        float2 wo1p = *reinterpret_cast<const float2*>(&sm[K2_WO1 + m0]);
        float ob0 = sm[K2_OUTB + 0];
        float ob1 = sm[K2_OUTB + 1];

        float y0[8], y1[8];
#pragma unroll
        for (int r = 0; r < 8; r++) {
            float2 ar = unpack2(A[r][0]);
            float2 az = unpack2(A[r][1]);
            float2 an = unpack2(A[r][2]);
            float4 hov = *reinterpret_cast<const float4*>(
                &sm[K2_HBD + (wrow + r) * 128 + 2 * m0]);   // {ho0,ho0,ho1,ho1}

            float gir0 = fmaf(x1[r], wi1r.x, fmaf(x0[r], wi0r.x, bir.x));
            float giz0 = fmaf(x1[r], wi1z.x, fmaf(x0[r], wi0z.x, biz.x));
            float gin0 = fmaf(x1[r], wi1n.x, fmaf(x0[r], wi0n.x, bin.x));
            float rg0 = sigf(gir0 + ar.x + bhr.x);
            float ug0 = sigf(giz0 + az.x + bhz.x);
            float ng0 = tanhfast(fmaf(rg0, an.x + bhn.x, gin0));
            float hn0 = fmaf(ug0, hov.x - ng0, ng0);

            float gir1 = fmaf(x1[r], wi1r.y, fmaf(x0[r], wi0r.y, bir.y));
            float giz1 = fmaf(x1[r], wi1z.y, fmaf(x0[r], wi0z.y, biz.y));
            float gin1 = fmaf(x1[r], wi1n.y, fmaf(x0[r], wi0n.y, bin.y));
            float rg1 = sigf(gir1 + ar.y + bhr.y);
            float ug1 = sigf(giz1 + az.y + bhz.y);
            float ng1 = tanhfast(fmaf(rg1, an.y + bhn.y, gin1));
            float hn1 = fmaf(ug1, hov.z - ng1, ng1);

            *reinterpret_cast<float4*>(&sm[K2_HBD + (wrow + r) * 128 + 2 * m0])
                = make_float4(hn0, hn0, hn1, hn1);
            y0[r] = fmaf(hn1, wo0p.y, hn0 * wo0p.x);
            y1[r] = fmaf(hn1, wo1p.y, hn0 * wo1p.x);
        }

        // reduce y over 32 lanes (butterfly; all lanes end with full sums)
#pragma unroll
        for (int d = 1; d < 32; d <<= 1) {
#pragma unroll
            for (int r = 0; r < 8; r++) {
                y0[r] += __shfl_xor_sync(0xffffffffu, y0[r], d);
                y1[r] += __shfl_xor_sync(0xffffffffu, y1[r], d);
            }
        }
#pragma unroll
        for (int r = 0; r < 8; r++) {
            x0[r] += y0[r] + ob0;
            x1[r] += y1[r] + ob1;
        }

        if (lan < 8) {
            float ox0 = x0[0], ox1 = x1[0];
#pragma unroll
            for (int r = 1; r < 8; r++)
                if (lan == r) { ox0 = x0[r]; ox1 = x1[r]; }
            int grow = row0 + wrow + lan;
            if (grow < B)
                *reinterpret_cast<float2*>(out + ((size_t)grow * T + step) * 2)
                    = make_float2(ox0, ox1);
        }
        __syncwarp();
    }
}

extern "C" void kernel_launch(void* const* d_in, const int* in_sizes, int n_in,
                              void* d_out, int out_size) {
    (void)n_in;
    const float* token = (const float*)d_in[0];
    const float* whw   = (const float*)d_in[1];
    const float* whb   = (const float*)d_in[2];
    const float* wih   = (const float*)d_in[3];
    const float* whh   = (const float*)d_in[4];
    const float* bih   = (const float*)d_in[5];
    const float* bhh   = (const float*)d_in[6];
    const float* wow   = (const float*)d_in[7];
    const float* wob   = (const float*)d_in[8];

    int NE = in_sizes[1] / HID;          // 1024
    int B  = in_sizes[0] / NE;           // 131072
    int T  = out_size / (B * 2);         // 10

    cudaFuncSetAttribute((const void*)head_gemm,
                         cudaFuncAttributeMaxDynamicSharedMemorySize, K1_SMEMB);
    cudaFuncSetAttribute((const void*)gru_steps,
                         cudaFuncAttributeMaxDynamicSharedMemorySize, K2_SMEMB);

    int g1 = (B + 127) / 128;
    head_gemm<<<g1, 256, K1_SMEMB>>>(token, whw, whb, B, NE);

    int g2 = (B + 63) / 64;
    gru_steps<<<g2, 256, K2_SMEMB>>>(wih, whh, bih, bhh, wow, wob,
                                     (float*)d_out, B, T);
}

// round 13
// speedup vs baseline: 1.1419x; 1.1419x over previous
#include <cuda_runtime.h>
#include <cuda_bf16.h>
#include <cstdint>
#include <cstddef>

#define HID 64
#define G3  192

typedef unsigned long long ull;

// scratch for h0 between the two kernels (B=131072 rows x 64)
__device__ float g_h0[131072ull * 64];

__device__ __forceinline__ void fma2(ull& d, ull a, ull b) {
    asm("fma.rn.f32x2 %0, %1, %2, %0;" : "+l"(d) : "l"(a), "l"(b));
}
__device__ __forceinline__ float2 unpack2(ull v) {
    float2 f; asm("mov.b64 {%0, %1}, %2;" : "=f"(f.x), "=f"(f.y) : "l"(v)); return f;
}
__device__ __forceinline__ float sigf(float v)  { return 1.0f / (1.0f + __expf(-v)); }
__device__ __forceinline__ float tanhfast(float v) {
    return 1.0f - 2.0f / (__expf(2.0f * v) + 1.0f);
}

// ============================================================================
// K1: h0 = token @ whw^T + whb   (unchanged SIMT f32x2 GEMM from R9)
// ============================================================================
#define K1_TOK   0
#define K1_W1    8704
#define K1_SMEMF (8704 + 4224)
#define K1_SMEMB (K1_SMEMF * 4)

__global__ void __launch_bounds__(256, 2)
head_gemm(const float* __restrict__ token,
          const float* __restrict__ whw,
          const float* __restrict__ whb,
          int B, int NE)
{
    extern __shared__ float sm[];
    const int tid  = threadIdx.x;
    const int wid  = tid >> 5;
    const int lan  = tid & 31;
    const int m0   = 2 * lan;
    const int row0 = blockIdx.x * 128;
    const int wrow = wid * 16;

    ull acc[16][2];
#pragma unroll
    for (int r = 0; r < 16; r++) { acc[r][0] = 0ull; acc[r][1] = 0ull; }

    const int nch = NE >> 6;

    float4 tpf[8], wpf[4];
#pragma unroll
    for (int ii = 0; ii < 8; ii++) {
        int i = tid + ii * 256;
        int r = i >> 4, c4 = i & 15;
        int gr = row0 + r;
        tpf[ii] = make_float4(0.f, 0.f, 0.f, 0.f);
        if (gr < B)
            tpf[ii] = reinterpret_cast<const float4*>(token)[(size_t)gr * (NE >> 2) + c4];
    }
#pragma unroll
    for (int ii = 0; ii < 4; ii++) {
        int i = tid + ii * 256;
        int m = i >> 4, k4 = i & 15;
        wpf[ii] = reinterpret_cast<const float4*>(whw)[(size_t)m * (NE >> 2) + k4];
    }

#pragma unroll 1
    for (int kc = 0; kc < nch; kc++) {
        __syncthreads();
#pragma unroll
        for (int ii = 0; ii < 8; ii++) {
            int i = tid + ii * 256;
            int r = i >> 4, c4 = i & 15;
            *reinterpret_cast<float4*>(&sm[K1_TOK + r * 68 + c4 * 4]) = tpf[ii];
        }
#pragma unroll
        for (int ii = 0; ii < 4; ii++) {
            int i = tid + ii * 256;
            int m = i >> 4, k4 = i & 15;
            float4 v = wpf[ii];
            sm[K1_W1 + (2 * k4 + 0) * 132 + 2 * m + 0] = v.x;
            sm[K1_W1 + (2 * k4 + 0) * 132 + 2 * m + 1] = v.y;
            sm[K1_W1 + (2 * k4 + 1) * 132 + 2 * m + 0] = v.z;
            sm[K1_W1 + (2 * k4 + 1) * 132 + 2 * m + 1] = v.w;
        }
        __syncthreads();
        if (kc + 1 < nch) {
#pragma unroll
            for (int ii = 0; ii < 8; ii++) {
                int i = tid + ii * 256;
                int r = i >> 4, c4 = i & 15;
                int gr = row0 + r;
                tpf[ii] = make_float4(0.f, 0.f, 0.f, 0.f);
                if (gr < B)
                    tpf[ii] = reinterpret_cast<const float4*>(token)
                                  [(size_t)gr * (NE >> 2) + (kc + 1) * 16 + c4];
            }
#pragma unroll
            for (int ii = 0; ii < 4; ii++) {
                int i = tid + ii * 256;
                int m = i >> 4, k4 = i & 15;
                wpf[ii] = reinterpret_cast<const float4*>(whw)
                              [(size_t)m * (NE >> 2) + (kc + 1) * 16 + k4];
            }
        }
#pragma unroll
        for (int k2e = 0; k2e < 32; k2e += 2) {
            ulonglong2 wv0 = *reinterpret_cast<const ulonglong2*>(&sm[K1_W1 + k2e * 132 + 4 * lan]);
            ulonglong2 wv1 = *reinterpret_cast<const ulonglong2*>(&sm[K1_W1 + (k2e + 1) * 132 + 4 * lan]);
#pragma unroll
            for (int r = 0; r < 16; r++) {
                ulonglong2 tp = *reinterpret_cast<const ulonglong2*>(
                    &sm[K1_TOK + (wrow + r) * 68 + k2e * 2]);
                fma2(acc[r][0], tp.x, wv0.x);
                fma2(acc[r][1], tp.x, wv0.y);
                fma2(acc[r][0], tp.y, wv1.x);
                fma2(acc[r][1], tp.y, wv1.y);
            }
        }
    }

    float b0 = whb[m0], b1 = whb[m0 + 1];
#pragma unroll
    for (int r = 0; r < 16; r++) {
        int gr = row0 + wrow + r;
        if (gr < B) {
            float2 a0 = unpack2(acc[r][0]);
            float2 a1 = unpack2(acc[r][1]);
            *reinterpret_cast<float2*>(&g_h0[(size_t)gr * 64 + m0])
                = make_float2(a0.x + a0.y + b0, a1.x + a1.y + b1);
        }
    }
}

// ============================================================================
// K2: GRU recurrence on warp-level HMMA (mma.sync m16n8k16 bf16, hi/lo 3-pass)
//   Per block: 128 rows, 8 warps. Warp w owns output cols {8w..8w+7} of each
//   gate; Whh fragments live in registers (loaded once). h state in smem as
//   bf16 hi/lo, XOR-swizzled, double-buffered. x/bias terms are rank-2 ->
//   handled as scalars in the epilogue.
// ============================================================================
#define XBUF  0
#define YPW   1024
#define A0HI  10240
#define A0LO  26624
#define A1HI  43008
#define A1LO  59392
#define BHIo  75776
#define BLOo  100352
#define K2_SMEM 124928

__device__ __forceinline__ uint32_t s2u(const void* p) {
    uint32_t a;
    asm("{ .reg .u64 t; cvta.to.shared.u64 t, %1; cvt.u32.u64 %0, t; }" : "=r"(a) : "l"(p));
    return a;
}
__device__ __forceinline__ uint32_t swz(int row, int col) {   // row stride 128B, col in bf16
    return (uint32_t)(row * 128 + (((col >> 3) ^ (row & 7)) << 4) + ((col & 7) << 1));
}
__device__ __forceinline__ uint32_t pack_bf2(float a, float b) {
    unsigned short ua = __bfloat16_as_ushort(__float2bfloat16(a));
    unsigned short ub = __bfloat16_as_ushort(__float2bfloat16(b));
    return (uint32_t)ua | ((uint32_t)ub << 16);
}
__device__ __forceinline__ float bf_hi(float a) {
    return __bfloat162float(__float2bfloat16(a));
}
__device__ __forceinline__ float2 bf22f(uint32_t u) {
    __nv_bfloat162 t = *reinterpret_cast<__nv_bfloat162*>(&u);
    return make_float2(__low2float(t), __high2float(t));
}
__device__ __forceinline__ void lda4(uint32_t* a, uint32_t base, int mt, int kt, int lane) {
    int r     = (lane & 7) | (lane & 8);
    int row   = mt * 16 + r;
    int chunk = 2 * kt + (lane >> 4);
    uint32_t addr = base + (uint32_t)(row * 128 + ((chunk ^ (row & 7)) << 4));
    asm volatile("ldmatrix.sync.aligned.m8n8.x4.shared.b16 {%0,%1,%2,%3}, [%4];"
        : "=r"(a[0]), "=r"(a[1]), "=r"(a[2]), "=r"(a[3]) : "r"(addr) : "memory");
}
__device__ __forceinline__ void ldb2(uint32_t* b, uint32_t base, int n0, int kt, int lane) {
    int row   = n0 + (lane & 7);
    int chunk = 2 * kt + ((lane >> 3) & 1);
    uint32_t addr = base + (uint32_t)(row * 128 + ((chunk ^ (row & 7)) << 4));
    asm volatile("ldmatrix.sync.aligned.m8n8.x2.shared.b16 {%0,%1}, [%2];"
        : "=r"(b[0]), "=r"(b[1]) : "r"(addr) : "memory");
}
__device__ __forceinline__ void mma_bf16(float* d, const uint32_t* a, const uint32_t* b) {
    asm("mma.sync.aligned.m16n8k16.row.col.f32.bf16.bf16.f32 "
        "{%0,%1,%2,%3}, {%4,%5,%6,%7}, {%8,%9}, {%0,%1,%2,%3};"
        : "+f"(d[0]), "+f"(d[1]), "+f"(d[2]), "+f"(d[3])
        : "r"(a[0]), "r"(a[1]), "r"(a[2]), "r"(a[3]), "r"(b[0]), "r"(b[1]));
}

__global__ void __launch_bounds__(256, 1)
gru_mma(const float* __restrict__ wih,   // [192, 2]
        const float* __restrict__ whhg,  // [192, 64]
        const float* __restrict__ bihg,  // [192]
        const float* __restrict__ bhhg,  // [192]
        const float* __restrict__ wow,   // [2, 64]
        const float* __restrict__ wob,   // [2]
        float* __restrict__ out,         // [B, T, 2]
        int B, int T)
{
    extern __shared__ char smc[];
    const int tid  = threadIdx.x;
    const int w    = tid >> 5;
    const int lane = tid & 31;
    const int g    = lane >> 2;
    const int q    = lane & 3;
    const int c0   = 8 * w + 2 * q;       // this thread's first output col (per gate)
    const int row0 = blockIdx.x * 128;
    const uint32_t sb = s2u(smc);

    // zero x-buffer
    if (tid < 128)
        *reinterpret_cast<float2*>(smc + XBUF + tid * 8) = make_float2(0.f, 0.f);

    // stage Whh hi/lo into swizzled smem [192][64]
    for (int idx = tid; idx < G3 * 64; idx += 256) {
        int n = idx >> 6, k = idx & 63;
        float v  = whhg[idx];
        float vh = bf_hi(v);
        uint32_t off = swz(n, k);
        *reinterpret_cast<unsigned short*>(smc + BHIo + off)
            = __bfloat16_as_ushort(__float2bfloat16(vh));
        *reinterpret_cast<unsigned short*>(smc + BLOo + off)
            = __bfloat16_as_ushort(__float2bfloat16(v - vh));
    }

    // stage h0 hi/lo into A-buffer 0
#pragma unroll
    for (int ii = 0; ii < 8; ii++) {
        int idx = tid + ii * 256;
        int r  = idx >> 4, c4 = idx & 15;
        int gr = row0 + r;
        float4 v = make_float4(0.f, 0.f, 0.f, 0.f);
        if (gr < B)
            v = reinterpret_cast<const float4*>(g_h0)[(size_t)gr * 16 + c4];
        float xh = bf_hi(v.x), yh = bf_hi(v.y), zh = bf_hi(v.z), wh = bf_hi(v.w);
        uint32_t off = swz(r, c4 * 4);
        *reinterpret_cast<uint2*>(smc + A0HI + off)
            = make_uint2(pack_bf2(xh, yh), pack_bf2(zh, wh));
        *reinterpret_cast<uint2*>(smc + A0LO + off)
            = make_uint2(pack_bf2(v.x - xh, v.y - yh), pack_bf2(v.z - zh, v.w - wh));
    }
    __syncthreads();

    // weight fragments in registers (persistent): warp w cols 8w..8w+7 per gate
    uint32_t Bh[3][4][2], Bl[3][4][2];
#pragma unroll
    for (int gi = 0; gi < 3; gi++)
#pragma unroll
        for (int kt = 0; kt < 4; kt++) {
            ldb2(Bh[gi][kt], sb + BHIo, gi * 64 + 8 * w, kt, lane);
            ldb2(Bl[gi][kt], sb + BLOo, gi * 64 + 8 * w, kt, lane);
        }

    // per-thread epilogue tables for its 2 cols
    float wr0[2], wr1[2], br_[2], wz0[2], wz1[2], bz_[2];
    float wn0[2], wn1[2], bin_[2], bhn_[2], wo0_[2], wo1_[2];
#pragma unroll
    for (int j = 0; j < 2; j++) {
        int c = c0 + j;
        wr0[j] = wih[c * 2];          wr1[j] = wih[c * 2 + 1];
        br_[j] = bihg[c] + bhhg[c];
        wz0[j] = wih[(64 + c) * 2];   wz1[j] = wih[(64 + c) * 2 + 1];
        bz_[j] = bihg[64 + c] + bhhg[64 + c];
        wn0[j] = wih[(128 + c) * 2];  wn1[j] = wih[(128 + c) * 2 + 1];
        bin_[j] = bihg[128 + c];      bhn_[j] = bhhg[128 + c];
        wo0_[j] = wow[c];             wo1_[j] = wow[64 + c];
    }
    const float ob0 = wob[0], ob1 = wob[1];

    int p = 0;
#pragma unroll 1
    for (int step = 0; step < T; step++) {
        uint32_t rhiU = sb + (p ? A1HI : A0HI);
        uint32_t rloU = sb + (p ? A1LO : A0LO);
        char* rhiP = smc + (p ? A1HI : A0HI);
        char* rloP = smc + (p ? A1LO : A0LO);
        char* whiP = smc + (p ? A0HI : A1HI);
        char* wloP = smc + (p ? A0LO : A1LO);

#pragma unroll
        for (int mc = 0; mc < 4; mc++) {       // 2 m-tiles (32 rows) per chunk
            float D[2][3][4];
#pragma unroll
            for (int m2 = 0; m2 < 2; m2++)
#pragma unroll
                for (int gi = 0; gi < 3; gi++)
#pragma unroll
                    for (int e = 0; e < 4; e++) D[m2][gi][e] = 0.f;

#pragma unroll
            for (int m2 = 0; m2 < 2; m2++) {
                int mt = mc * 2 + m2;
#pragma unroll
                for (int kt = 0; kt < 4; kt++) {
                    uint32_t ah[4], al[4];
                    lda4(ah, rhiU, mt, kt, lane);
                    lda4(al, rloU, mt, kt, lane);
#pragma unroll
                    for (int gi = 0; gi < 3; gi++) {
                        mma_bf16(D[m2][gi], ah, Bh[gi][kt]);
                        mma_bf16(D[m2][gi], al, Bh[gi][kt]);
                        mma_bf16(D[m2][gi], ah, Bl[gi][kt]);
                    }
                }
            }

            // epilogue for rows of this chunk
#pragma unroll
            for (int m2 = 0; m2 < 2; m2++) {
                int mt = mc * 2 + m2;
                int r0 = mt * 16 + g;
                int r1 = r0 + 8;
                float2 xA = *reinterpret_cast<const float2*>(smc + XBUF + r0 * 8);
                float2 xB = *reinterpret_cast<const float2*>(smc + XBUF + r1 * 8);
                float yv[4];
#pragma unroll
                for (int rowi = 0; rowi < 2; rowi++) {
                    int rr = rowi ? r1 : r0;
                    float xx0 = rowi ? xB.x : xA.x;
                    float xx1 = rowi ? xB.y : xA.y;
                    uint32_t offh = swz(rr, c0);
                    float2 hhi = bf22f(*reinterpret_cast<const uint32_t*>(rhiP + offh));
                    float2 hlo = bf22f(*reinterpret_cast<const uint32_t*>(rloP + offh));
                    float hn2[2];
#pragma unroll
                    for (int j = 0; j < 2; j++) {
                        float dr = D[m2][0][rowi * 2 + j];
                        float dz = D[m2][1][rowi * 2 + j];
                        float dn = D[m2][2][rowi * 2 + j];
                        float rg = sigf(fmaf(xx1, wr1[j], fmaf(xx0, wr0[j], br_[j])) + dr);
                        float ug = sigf(fmaf(xx1, wz1[j], fmaf(xx0, wz0[j], bz_[j])) + dz);
                        float gn = fmaf(xx1, wn1[j], fmaf(xx0, wn0[j], bin_[j]));
                        float ng = tanhfast(fmaf(rg, dn + bhn_[j], gn));
                        float hold = j ? (hhi.y + hlo.y) : (hhi.x + hlo.x);
                        hn2[j] = fmaf(ug, hold - ng, ng);
                    }
                    float h0h = bf_hi(hn2[0]);
                    float h1h = bf_hi(hn2[1]);
                    *reinterpret_cast<uint32_t*>(whiP + offh) = pack_bf2(h0h, h1h);
                    *reinterpret_cast<uint32_t*>(wloP + offh)
                        = pack_bf2(hn2[0] - h0h, hn2[1] - h1h);
                    yv[rowi * 2 + 0] = fmaf(hn2[1], wo0_[1], hn2[0] * wo0_[0]);
                    yv[rowi * 2 + 1] = fmaf(hn2[1], wo1_[1], hn2[0] * wo1_[0]);
                }
                // sum over the 4 q-lanes (same rows) -> q==0 holds warp partial
#pragma unroll
                for (int d = 1; d < 4; d <<= 1)
#pragma unroll
                    for (int u = 0; u < 4; u++)
                        yv[u] += __shfl_xor_sync(0xffffffffu, yv[u], d);
                if (q == 0) {
                    *reinterpret_cast<float2*>(smc + YPW + (w * 128 + r0) * 8)
                        = make_float2(yv[0], yv[1]);
                    *reinterpret_cast<float2*>(smc + YPW + (w * 128 + r1) * 8)
                        = make_float2(yv[2], yv[3]);
                }
            }
        }
        __syncthreads();

        if (tid < 128) {
            int row = tid;
            float y0 = 0.f, y1 = 0.f;
#pragma unroll
            for (int ww = 0; ww < 8; ww++) {
                float2 pv = *reinterpret_cast<const float2*>(smc + YPW + (ww * 128 + row) * 8);
                y0 += pv.x;
                y1 += pv.y;
            }
            float2 xv = *reinterpret_cast<float2*>(smc + XBUF + row * 8);
            xv.x += y0 + ob0;
            xv.y += y1 + ob1;
            *reinterpret_cast<float2*>(smc + XBUF + row * 8) = xv;
            int grow = row0 + row;
            if (grow < B)
                *reinterpret_cast<float2*>(out + ((size_t)grow * T + step) * 2) = xv;
        }
        __syncthreads();
        p ^= 1;
    }
}

extern "C" void kernel_launch(void* const* d_in, const int* in_sizes, int n_in,
                              void* d_out, int out_size) {
    (void)n_in;
    const float* token = (const float*)d_in[0];
    const float* whw   = (const float*)d_in[1];
    const float* whb   = (const float*)d_in[2];
    const float* wih   = (const float*)d_in[3];
    const float* whh   = (const float*)d_in[4];
    const float* bih   = (const float*)d_in[5];
    const float* bhh   = (const float*)d_in[6];
    const float* wow   = (const float*)d_in[7];
    const float* wob   = (const float*)d_in[8];

    int NE = in_sizes[1] / HID;          // 1024
    int B  = in_sizes[0] / NE;           // 131072
    int T  = out_size / (B * 2);         // 10

    cudaFuncSetAttribute((const void*)head_gemm,
                         cudaFuncAttributeMaxDynamicSharedMemorySize, K1_SMEMB);
    cudaFuncSetAttribute((const void*)gru_mma,
                         cudaFuncAttributeMaxDynamicSharedMemorySize, K2_SMEM);

    int g1 = (B + 127) / 128;
    head_gemm<<<g1, 256, K1_SMEMB>>>(token, whw, whb, B, NE);

    int g2 = (B + 127) / 128;
    gru_mma<<<g2, 256, K2_SMEM>>>(wih, whh, bih, bhh, wow, wob,
                                  (float*)d_out, B, T);
}

// round 14
// speedup vs baseline: 1.9037x; 1.6671x over previous
#include <cuda_runtime.h>
#include <cuda_bf16.h>
#include <cstdint>
#include <cstddef>

#define HID 64
#define G3  192

typedef unsigned long long ull;

// scratch for h0 between the two kernels (B=131072 rows x 64)
__device__ float g_h0[131072ull * 64];

__device__ __forceinline__ float sigf(float v)  { return 1.0f / (1.0f + __expf(-v)); }
__device__ __forceinline__ float tanhfast(float v) {
    return 1.0f - 2.0f / (__expf(2.0f * v) + 1.0f);
}
__device__ __forceinline__ uint32_t s2u(const void* p) {
    uint32_t a;
    asm("{ .reg .u64 t; cvta.to.shared.u64 t, %1; cvt.u32.u64 %0, t; }" : "=r"(a) : "l"(p));
    return a;
}
__device__ __forceinline__ uint32_t swz(int row, int col) {   // row stride 128B, col in bf16
    return (uint32_t)(row * 128 + (((col >> 3) ^ (row & 7)) << 4) + ((col & 7) << 1));
}
__device__ __forceinline__ uint32_t pack_bf2(float a, float b) {
    unsigned short ua = __bfloat16_as_ushort(__float2bfloat16(a));
    unsigned short ub = __bfloat16_as_ushort(__float2bfloat16(b));
    return (uint32_t)ua | ((uint32_t)ub << 16);
}
__device__ __forceinline__ float bf_hi(float a) {
    return __bfloat162float(__float2bfloat16(a));
}
__device__ __forceinline__ float2 bf22f(uint32_t u) {
    __nv_bfloat162 t = *reinterpret_cast<__nv_bfloat162*>(&u);
    return make_float2(__low2float(t), __high2float(t));
}
__device__ __forceinline__ void lda4(uint32_t* a, uint32_t base, int mt, int kt, int lane) {
    int r     = (lane & 7) | (lane & 8);
    int row   = mt * 16 + r;
    int chunk = 2 * kt + (lane >> 4);
    uint32_t addr = base + (uint32_t)(row * 128 + ((chunk ^ (row & 7)) << 4));
    asm volatile("ldmatrix.sync.aligned.m8n8.x4.shared.b16 {%0,%1,%2,%3}, [%4];"
        : "=r"(a[0]), "=r"(a[1]), "=r"(a[2]), "=r"(a[3]) : "r"(addr) : "memory");
}
__device__ __forceinline__ void ldb2(uint32_t* b, uint32_t base, int n0, int kt, int lane) {
    int row   = n0 + (lane & 7);
    int chunk = 2 * kt + ((lane >> 3) & 1);
    uint32_t addr = base + (uint32_t)(row * 128 + ((chunk ^ (row & 7)) << 4));
    asm volatile("ldmatrix.sync.aligned.m8n8.x2.shared.b16 {%0,%1}, [%2];"
        : "=r"(b[0]), "=r"(b[1]) : "r"(addr) : "memory");
}
__device__ __forceinline__ void mma_bf16(float* d, const uint32_t* a, const uint32_t* b) {
    asm("mma.sync.aligned.m16n8k16.row.col.f32.bf16.bf16.f32 "
        "{%0,%1,%2,%3}, {%4,%5,%6,%7}, {%8,%9}, {%0,%1,%2,%3};"
        : "+f"(d[0]), "+f"(d[1]), "+f"(d[2]), "+f"(d[3])
        : "r"(a[0]), "r"(a[1]), "r"(a[2]), "r"(a[3]), "r"(b[0]), "r"(b[1]));
}

// ============================================================================
// K1: h0 = token @ whw^T + whb  on HMMA (bf16 hi/lo 3-pass).
//   Block = 128 rows, 8 warps; warp w owns m-tile rows w*16..w*16+15.
//   16 k-chunks of 64; token chunk register-prefetched, converted to bf16
//   hi/lo swizzled smem; W chunk loaded per chunk (L2-resident).
// ============================================================================
#define H1_TOKHI 0
#define H1_TOKLO 16384
#define H1_WHI   32768
#define H1_WLO   40960
#define H1_SMEM  49152

__global__ void __launch_bounds__(256, 2)
head_tc(const float* __restrict__ token,
        const float* __restrict__ whw,
        const float* __restrict__ whb,
        int B, int NE)
{
    extern __shared__ char smc[];
    const uint32_t sb = s2u(smc);
    const int tid  = threadIdx.x;
    const int w    = tid >> 5;
    const int lane = tid & 31;
    const int g    = lane >> 2;
    const int q    = lane & 3;
    const int row0 = blockIdx.x * 128;

    float D[8][4];
#pragma unroll
    for (int nt = 0; nt < 8; nt++)
#pragma unroll
        for (int e = 0; e < 4; e++) D[nt][e] = 0.f;

    const int nch = NE >> 6;    // 16

    float4 tpf[8];
#pragma unroll
    for (int ii = 0; ii < 8; ii++) {
        int i = tid + ii * 256;
        int r = i >> 4, c4 = i & 15;
        int gr = row0 + r;
        tpf[ii] = make_float4(0.f, 0.f, 0.f, 0.f);
        if (gr < B)
            tpf[ii] = reinterpret_cast<const float4*>(token)[(size_t)gr * (NE >> 2) + c4];
    }

#pragma unroll 1
    for (int kc = 0; kc < nch; kc++) {
        __syncthreads();
        // token chunk -> bf16 hi/lo swizzled smem
#pragma unroll
        for (int ii = 0; ii < 8; ii++) {
            int i = tid + ii * 256;
            int r = i >> 4, c4 = i & 15;
            float4 v = tpf[ii];
            float xh = bf_hi(v.x), yh = bf_hi(v.y), zh = bf_hi(v.z), wh = bf_hi(v.w);
            uint32_t off = swz(r, c4 * 4);
            *reinterpret_cast<uint2*>(smc + H1_TOKHI + off)
                = make_uint2(pack_bf2(xh, yh), pack_bf2(zh, wh));
            *reinterpret_cast<uint2*>(smc + H1_TOKLO + off)
                = make_uint2(pack_bf2(v.x - xh, v.y - yh), pack_bf2(v.z - zh, v.w - wh));
        }
        // W chunk -> bf16 hi/lo swizzled smem (rows m=0..63, cols kc*64..)
#pragma unroll
        for (int ii = 0; ii < 4; ii++) {
            int i = tid + ii * 256;
            int m = i >> 4, k4 = i & 15;
            float4 v = reinterpret_cast<const float4*>(whw)[(size_t)m * (NE >> 2) + kc * 16 + k4];
            float xh = bf_hi(v.x), yh = bf_hi(v.y), zh = bf_hi(v.z), wh = bf_hi(v.w);
            uint32_t off = swz(m, k4 * 4);
            *reinterpret_cast<uint2*>(smc + H1_WHI + off)
                = make_uint2(pack_bf2(xh, yh), pack_bf2(zh, wh));
            *reinterpret_cast<uint2*>(smc + H1_WLO + off)
                = make_uint2(pack_bf2(v.x - xh, v.y - yh), pack_bf2(v.z - zh, v.w - wh));
        }
        __syncthreads();
        // prefetch next token chunk
        if (kc + 1 < nch) {
#pragma unroll
            for (int ii = 0; ii < 8; ii++) {
                int i = tid + ii * 256;
                int r = i >> 4, c4 = i & 15;
                int gr = row0 + r;
                tpf[ii] = make_float4(0.f, 0.f, 0.f, 0.f);
                if (gr < B)
                    tpf[ii] = reinterpret_cast<const float4*>(token)
                                  [(size_t)gr * (NE >> 2) + (kc + 1) * 16 + c4];
            }
        }
        // MMA: warp w = m-tile w
#pragma unroll
        for (int kt = 0; kt < 4; kt++) {
            uint32_t ah[4], al[4];
            lda4(ah, sb + H1_TOKHI, w, kt, lane);
            lda4(al, sb + H1_TOKLO, w, kt, lane);
#pragma unroll
            for (int nt = 0; nt < 8; nt++) {
                uint32_t bh[2], bl[2];
                ldb2(bh, sb + H1_WHI, nt * 8, kt, lane);
                ldb2(bl, sb + H1_WLO, nt * 8, kt, lane);
                mma_bf16(D[nt], ah, bh);
                mma_bf16(D[nt], al, bh);
                mma_bf16(D[nt], ah, bl);
            }
        }
    }

    // epilogue: rows r0 = w*16+g, r1 = r0+8; cols c = nt*8 + 2q + {0,1}
#pragma unroll
    for (int nt = 0; nt < 8; nt++) {
        int c = nt * 8 + 2 * q;
        float b0 = whb[c], b1 = whb[c + 1];
        int gr0 = row0 + w * 16 + g;
        int gr1 = gr0 + 8;
        if (gr0 < B)
            *reinterpret_cast<float2*>(&g_h0[(size_t)gr0 * 64 + c])
                = make_float2(D[nt][0] + b0, D[nt][1] + b1);
        if (gr1 < B)
            *reinterpret_cast<float2*>(&g_h0[(size_t)gr1 * 64 + c])
                = make_float2(D[nt][2] + b0, D[nt][3] + b1);
    }
}

// ============================================================================
// K2: GRU recurrence on warp-level HMMA (unchanged math from R13), now with
//   2 blocks/SM: epilogue constants in a smem table (ETAB), Whh staged hi/lo
//   through ONE 24KB region aliased over the A1 buffers (smem 125KB -> 77KB),
//   __launch_bounds__(256,2).
// ============================================================================
#define XBUF  0
#define YPW   1024
#define ETAB  9216
#define A0HI  13312
#define A0LO  29696
#define A1HI  46080
#define A1LO  62464
#define BSTG  46080
#define K2_SMEM 78848

__global__ void __launch_bounds__(256, 2)
gru_mma(const float* __restrict__ wih,   // [192, 2]
        const float* __restrict__ whhg,  // [192, 64]
        const float* __restrict__ bihg,  // [192]
        const float* __restrict__ bhhg,  // [192]
        const float* __restrict__ wow,   // [2, 64]
        const float* __restrict__ wob,   // [2]
        float* __restrict__ out,         // [B, T, 2]
        int B, int T)
{
    extern __shared__ char smc[];
    const int tid  = threadIdx.x;
    const int w    = tid >> 5;
    const int lane = tid & 31;
    const int g    = lane >> 2;
    const int q    = lane & 3;
    const int c0   = 8 * w + 2 * q;       // this thread's first output col (per gate)
    const int row0 = blockIdx.x * 128;
    const uint32_t sb = s2u(smc);

    // zero x-buffer
    if (tid < 128)
        *reinterpret_cast<float2*>(smc + XBUF + tid * 8) = make_float2(0.f, 0.f);

    // epilogue constant table: 64 cols x 4 float4
    for (int c = tid; c < 64; c += 256) {
        char* e = smc + ETAB + c * 64;
        *reinterpret_cast<float4*>(e + 0)
            = make_float4(wih[c * 2], wih[c * 2 + 1], bihg[c] + bhhg[c], 0.f);
        *reinterpret_cast<float4*>(e + 16)
            = make_float4(wih[(64 + c) * 2], wih[(64 + c) * 2 + 1],
                          bihg[64 + c] + bhhg[64 + c], 0.f);
        *reinterpret_cast<float4*>(e + 32)
            = make_float4(wih[(128 + c) * 2], wih[(128 + c) * 2 + 1],
                          bihg[128 + c], bhhg[128 + c]);
        *reinterpret_cast<float4*>(e + 48)
            = make_float4(wow[c], wow[64 + c], 0.f, 0.f);
    }

    // ---- phase 1: stage Whh HI into BSTG, load hi fragments ----
    for (int idx = tid; idx < G3 * 64; idx += 256) {
        int n = idx >> 6, k = idx & 63;
        float v = whhg[idx];
        *reinterpret_cast<unsigned short*>(smc + BSTG + swz(n, k))
            = __bfloat16_as_ushort(__float2bfloat16(bf_hi(v)));
    }
    __syncthreads();
    uint32_t Bh[3][4][2], Bl[3][4][2];
#pragma unroll
    for (int gi = 0; gi < 3; gi++)
#pragma unroll
        for (int kt = 0; kt < 4; kt++)
            ldb2(Bh[gi][kt], sb + BSTG, gi * 64 + 8 * w, kt, lane);
    __syncthreads();

    // ---- phase 2: stage Whh LO into BSTG; also stage h0 hi/lo into A0 ----
    for (int idx = tid; idx < G3 * 64; idx += 256) {
        int n = idx >> 6, k = idx & 63;
        float v = whhg[idx];
        *reinterpret_cast<unsigned short*>(smc + BSTG + swz(n, k))
            = __bfloat16_as_ushort(__float2bfloat16(v - bf_hi(v)));
    }
#pragma unroll
    for (int ii = 0; ii < 8; ii++) {
        int idx = tid + ii * 256;
        int r  = idx >> 4, c4 = idx & 15;
        int gr = row0 + r;
        float4 v = make_float4(0.f, 0.f, 0.f, 0.f);
        if (gr < B)
            v = reinterpret_cast<const float4*>(g_h0)[(size_t)gr * 16 + c4];
        float xh = bf_hi(v.x), yh = bf_hi(v.y), zh = bf_hi(v.z), wh = bf_hi(v.w);
        uint32_t off = swz(r, c4 * 4);
        *reinterpret_cast<uint2*>(smc + A0HI + off)
            = make_uint2(pack_bf2(xh, yh), pack_bf2(zh, wh));
        *reinterpret_cast<uint2*>(smc + A0LO + off)
            = make_uint2(pack_bf2(v.x - xh, v.y - yh), pack_bf2(v.z - zh, v.w - wh));
    }
    __syncthreads();
#pragma unroll
    for (int gi = 0; gi < 3; gi++)
#pragma unroll
        for (int kt = 0; kt < 4; kt++)
            ldb2(Bl[gi][kt], sb + BSTG, gi * 64 + 8 * w, kt, lane);
    __syncthreads();

    const float ob0 = wob[0], ob1 = wob[1];

    int p = 0;
#pragma unroll 1
    for (int step = 0; step < T; step++) {
        uint32_t rhiU = sb + (p ? A1HI : A0HI);
        uint32_t rloU = sb + (p ? A1LO : A0LO);
        char* rhiP = smc + (p ? A1HI : A0HI);
        char* rloP = smc + (p ? A1LO : A0LO);
        char* whiP = smc + (p ? A0HI : A1HI);
        char* wloP = smc + (p ? A0LO : A1LO);

#pragma unroll
        for (int mc = 0; mc < 4; mc++) {       // 2 m-tiles (32 rows) per chunk
            float D[2][3][4];
#pragma unroll
            for (int m2 = 0; m2 < 2; m2++)
#pragma unroll
                for (int gi = 0; gi < 3; gi++)
#pragma unroll
                    for (int e = 0; e < 4; e++) D[m2][gi][e] = 0.f;

#pragma unroll
            for (int m2 = 0; m2 < 2; m2++) {
                int mt = mc * 2 + m2;
#pragma unroll
                for (int kt = 0; kt < 4; kt++) {
                    uint32_t ah[4], al[4];
                    lda4(ah, rhiU, mt, kt, lane);
                    lda4(al, rloU, mt, kt, lane);
#pragma unroll
                    for (int gi = 0; gi < 3; gi++) {
                        mma_bf16(D[m2][gi], ah, Bh[gi][kt]);
                        mma_bf16(D[m2][gi], al, Bh[gi][kt]);
                        mma_bf16(D[m2][gi], ah, Bl[gi][kt]);
                    }
                }
            }

            // epilogue for rows of this chunk
#pragma unroll
            for (int m2 = 0; m2 < 2; m2++) {
                int mt = mc * 2 + m2;
                int r0 = mt * 16 + g;
                int r1 = r0 + 8;
                // constants for this thread's two columns
                const char* eA = smc + ETAB + (c0 + 0) * 64;
                const char* eB = smc + ETAB + (c0 + 1) * 64;
                float4 a0 = *reinterpret_cast<const float4*>(eA + 0);
                float4 a1 = *reinterpret_cast<const float4*>(eA + 16);
                float4 a2 = *reinterpret_cast<const float4*>(eA + 32);
                float4 a3 = *reinterpret_cast<const float4*>(eA + 48);
                float4 b0 = *reinterpret_cast<const float4*>(eB + 0);
                float4 b1 = *reinterpret_cast<const float4*>(eB + 16);
                float4 b2 = *reinterpret_cast<const float4*>(eB + 32);
                float4 b3 = *reinterpret_cast<const float4*>(eB + 48);
                float2 xA = *reinterpret_cast<const float2*>(smc + XBUF + r0 * 8);
                float2 xB = *reinterpret_cast<const float2*>(smc + XBUF + r1 * 8);
                float yv[4];
#pragma unroll
                for (int rowi = 0; rowi < 2; rowi++) {
                    int rr = rowi ? r1 : r0;
                    float xx0 = rowi ? xB.x : xA.x;
                    float xx1 = rowi ? xB.y : xA.y;
                    uint32_t offh = swz(rr, c0);
                    float2 hhi = bf22f(*reinterpret_cast<const uint32_t*>(rhiP + offh));
                    float2 hlo = bf22f(*reinterpret_cast<const uint32_t*>(rloP + offh));

                    float dr0 = D[m2][0][rowi * 2 + 0];
                    float dz0 = D[m2][1][rowi * 2 + 0];
                    float dn0 = D[m2][2][rowi * 2 + 0];
                    float rg0 = sigf(fmaf(xx1, a0.y, fmaf(xx0, a0.x, a0.z)) + dr0);
                    float ug0 = sigf(fmaf(xx1, a1.y, fmaf(xx0, a1.x, a1.z)) + dz0);
                    float gn0 = fmaf(xx1, a2.y, fmaf(xx0, a2.x, a2.z));
                    float ng0 = tanhfast(fmaf(rg0, dn0 + a2.w, gn0));
                    float hn0 = fmaf(ug0, (hhi.x + hlo.x) - ng0, ng0);

                    float dr1 = D[m2][0][rowi * 2 + 1];
                    float dz1 = D[m2][1][rowi * 2 + 1];
                    float dn1 = D[m2][2][rowi * 2 + 1];
                    float rg1 = sigf(fmaf(xx1, b0.y, fmaf(xx0, b0.x, b0.z)) + dr1);
                    float ug1 = sigf(fmaf(xx1, b1.y, fmaf(xx0, b1.x, b1.z)) + dz1);
                    float gn1 = fmaf(xx1, b2.y, fmaf(xx0, b2.x, b2.z));
                    float ng1 = tanhfast(fmaf(rg1, dn1 + b2.w, gn1));
                    float hn1 = fmaf(ug1, (hhi.y + hlo.y) - ng1, ng1);

                    float h0h = bf_hi(hn0);
                    float h1h = bf_hi(hn1);
                    *reinterpret_cast<uint32_t*>(whiP + offh) = pack_bf2(h0h, h1h);
                    *reinterpret_cast<uint32_t*>(wloP + offh)
                        = pack_bf2(hn0 - h0h, hn1 - h1h);
                    yv[rowi * 2 + 0] = fmaf(hn1, b3.x, hn0 * a3.x);
                    yv[rowi * 2 + 1] = fmaf(hn1, b3.y, hn0 * a3.y);
                }
                // sum over the 4 q-lanes (same rows) -> q==0 holds warp partial
#pragma unroll
                for (int d = 1; d < 4; d <<= 1)
#pragma unroll
                    for (int u = 0; u < 4; u++)
                        yv[u] += __shfl_xor_sync(0xffffffffu, yv[u], d);
                if (q == 0) {
                    *reinterpret_cast<float2*>(smc + YPW + (w * 128 + r0) * 8)
                        = make_float2(yv[0], yv[1]);
                    *reinterpret_cast<float2*>(smc + YPW + (w * 128 + r1) * 8)
                        = make_float2(yv[2], yv[3]);
                }
            }
        }
        __syncthreads();

        if (tid < 128) {
            int row = tid;
            float y0 = 0.f, y1 = 0.f;
#pragma unroll
            for (int ww = 0; ww < 8; ww++) {
                float2 pv = *reinterpret_cast<const float2*>(smc + YPW + (ww * 128 + row) * 8);
                y0 += pv.x;
                y1 += pv.y;
            }
            float2 xv = *reinterpret_cast<float2*>(smc + XBUF + row * 8);
            xv.x += y0 + ob0;
            xv.y += y1 + ob1;
            *reinterpret_cast<float2*>(smc + XBUF + row * 8) = xv;
            int grow = row0 + row;
            if (grow < B)
                *reinterpret_cast<float2*>(out + ((size_t)grow * T + step) * 2) = xv;
        }
        __syncthreads();
        p ^= 1;
    }
}

extern "C" void kernel_launch(void* const* d_in, const int* in_sizes, int n_in,
                              void* d_out, int out_size) {
    (void)n_in;
    const float* token = (const float*)d_in[0];
    const float* whw   = (const float*)d_in[1];
    const float* whb   = (const float*)d_in[2];
    const float* wih   = (const float*)d_in[3];
    const float* whh   = (const float*)d_in[4];
    const float* bih   = (const float*)d_in[5];
    const float* bhh   = (const float*)d_in[6];
    const float* wow   = (const float*)d_in[7];
    const float* wob   = (const float*)d_in[8];

    int NE = in_sizes[1] / HID;          // 1024
    int B  = in_sizes[0] / NE;           // 131072
    int T  = out_size / (B * 2);         // 10

    cudaFuncSetAttribute((const void*)head_tc,
                         cudaFuncAttributeMaxDynamicSharedMemorySize, H1_SMEM);
    cudaFuncSetAttribute((const void*)gru_mma,
                         cudaFuncAttributeMaxDynamicSharedMemorySize, K2_SMEM);

    int g1 = (B + 127) / 128;
    head_tc<<<g1, 256, H1_SMEM>>>(token, whw, whb, B, NE);

    int g2 = (B + 127) / 128;
    gru_mma<<<g2, 256, K2_SMEM>>>(wih, whh, bih, bhh, wow, wob,
                                  (float*)d_out, B, T);
}

// round 15
// speedup vs baseline: 2.2043x; 1.1579x over previous
#include <cuda_runtime.h>
#include <cuda_bf16.h>
#include <cstdint>
#include <cstddef>

#define HID 64
#define G3  192

typedef unsigned long long ull;

// scratch for h0 between the two kernels (B=131072 rows x 64)
__device__ float g_h0[131072ull * 64];

__device__ __forceinline__ float sigf(float v)  { return 1.0f / (1.0f + __expf(-v)); }
__device__ __forceinline__ float tanhfast(float v) {
    return 1.0f - 2.0f / (__expf(2.0f * v) + 1.0f);
}
__device__ __forceinline__ uint32_t s2u(const void* p) {
    uint32_t a;
    asm("{ .reg .u64 t; cvta.to.shared.u64 t, %1; cvt.u32.u64 %0, t; }" : "=r"(a) : "l"(p));
    return a;
}
__device__ __forceinline__ uint32_t swz(int row, int col) {   // row stride 128B, col in bf16
    return (uint32_t)(row * 128 + (((col >> 3) ^ (row & 7)) << 4) + ((col & 7) << 1));
}
__device__ __forceinline__ uint32_t pack_bf2(float a, float b) {
    unsigned short ua = __bfloat16_as_ushort(__float2bfloat16(a));
    unsigned short ub = __bfloat16_as_ushort(__float2bfloat16(b));
    return (uint32_t)ua | ((uint32_t)ub << 16);
}
__device__ __forceinline__ float bf_hi(float a) {
    return __bfloat162float(__float2bfloat16(a));
}
__device__ __forceinline__ float2 bf22f(uint32_t u) {
    __nv_bfloat162 t = *reinterpret_cast<__nv_bfloat162*>(&u);
    return make_float2(__low2float(t), __high2float(t));
}
__device__ __forceinline__ void lda4a(uint32_t* a, uint32_t addr) {
    asm volatile("ldmatrix.sync.aligned.m8n8.x4.shared.b16 {%0,%1,%2,%3}, [%4];"
        : "=r"(a[0]), "=r"(a[1]), "=r"(a[2]), "=r"(a[3]) : "r"(addr) : "memory");
}
__device__ __forceinline__ void ldb2(uint32_t* b, uint32_t base, int n0, int kt, int lane) {
    int row   = n0 + (lane & 7);
    int chunk = 2 * kt + ((lane >> 3) & 1);
    uint32_t addr = base + (uint32_t)(row * 128 + ((chunk ^ (row & 7)) << 4));
    asm volatile("ldmatrix.sync.aligned.m8n8.x2.shared.b16 {%0,%1}, [%2];"
        : "=r"(b[0]), "=r"(b[1]) : "r"(addr) : "memory");
}
__device__ __forceinline__ void mma_bf16(float* d, const uint32_t* a, const uint32_t* b) {
    asm("mma.sync.aligned.m16n8k16.row.col.f32.bf16.bf16.f32 "
        "{%0,%1,%2,%3}, {%4,%5,%6,%7}, {%8,%9}, {%0,%1,%2,%3};"
        : "+f"(d[0]), "+f"(d[1]), "+f"(d[2]), "+f"(d[3])
        : "r"(a[0]), "r"(a[1]), "r"(a[2]), "r"(a[3]), "r"(b[0]), "r"(b[1]));
}

// ============================================================================
// K1: h0 = token @ whw^T + whb  on HMMA (bf16 hi/lo 3-pass), double-buffered.
// ============================================================================
#define HB_TOKHI 0
#define HB_TOKLO 16384
#define HB_WHI   32768
#define HB_WLO   40960
#define H1_BUF   49152
#define H1_SMEM  98304

__global__ void __launch_bounds__(256, 2)
head_tc(const float* __restrict__ token,
        const float* __restrict__ whw,
        const float* __restrict__ whb,
        int B, int NE)
{
    extern __shared__ char smc[];
    const uint32_t sb = s2u(smc);
    const int tid  = threadIdx.x;
    const int w    = tid >> 5;
    const int lane = tid & 31;
    const int g    = lane >> 2;
    const int q    = lane & 3;
    const int row0 = blockIdx.x * 128;

    const uint32_t Abase = (uint32_t)((((lane & 7) | (lane & 8))) * 128);
    const int hi16 = lane >> 4;
    const int low7 = lane & 7;

    float D[8][4];
#pragma unroll
    for (int nt = 0; nt < 8; nt++)
#pragma unroll
        for (int e = 0; e < 4; e++) D[nt][e] = 0.f;

    const int nch = NE >> 6;    // 16

    float4 tpf[8], wpf[4];
    // preload chunk 0
#pragma unroll
    for (int ii = 0; ii < 8; ii++) {
        int i = tid + ii * 256;
        int r = i >> 4, c4 = i & 15;
        int gr = row0 + r;
        tpf[ii] = make_float4(0.f, 0.f, 0.f, 0.f);
        if (gr < B)
            tpf[ii] = reinterpret_cast<const float4*>(token)[(size_t)gr * (NE >> 2) + c4];
    }
#pragma unroll
    for (int ii = 0; ii < 4; ii++) {
        int i = tid + ii * 256;
        int m = i >> 4, k4 = i & 15;
        wpf[ii] = reinterpret_cast<const float4*>(whw)[(size_t)m * (NE >> 2) + k4];
    }
    // store chunk 0 into buffer 0
    {
        char* buf = smc;
#pragma unroll
        for (int ii = 0; ii < 8; ii++) {
            int i = tid + ii * 256;
            int r = i >> 4, c4 = i & 15;
            float4 v = tpf[ii];
            float xh = bf_hi(v.x), yh = bf_hi(v.y), zh = bf_hi(v.z), wh = bf_hi(v.w);
            uint32_t off = swz(r, c4 * 4);
            *reinterpret_cast<uint2*>(buf + HB_TOKHI + off)
                = make_uint2(pack_bf2(xh, yh), pack_bf2(zh, wh));
            *reinterpret_cast<uint2*>(buf + HB_TOKLO + off)
                = make_uint2(pack_bf2(v.x - xh, v.y - yh), pack_bf2(v.z - zh, v.w - wh));
        }
#pragma unroll
        for (int ii = 0; ii < 4; ii++) {
            int i = tid + ii * 256;
            int m = i >> 4, k4 = i & 15;
            float4 v = wpf[ii];
            float xh = bf_hi(v.x), yh = bf_hi(v.y), zh = bf_hi(v.z), wh = bf_hi(v.w);
            uint32_t off = swz(m, k4 * 4);
            *reinterpret_cast<uint2*>(buf + HB_WHI + off)
                = make_uint2(pack_bf2(xh, yh), pack_bf2(zh, wh));
            *reinterpret_cast<uint2*>(buf + HB_WLO + off)
                = make_uint2(pack_bf2(v.x - xh, v.y - yh), pack_bf2(v.z - zh, v.w - wh));
        }
    }
    __syncthreads();

    int p = 0;
#pragma unroll 1
    for (int kc = 0; kc < nch; kc++) {
        // prefetch next chunk (LDG overlaps MMA)
        if (kc + 1 < nch) {
#pragma unroll
            for (int ii = 0; ii < 8; ii++) {
                int i = tid + ii * 256;
                int r = i >> 4, c4 = i & 15;
                int gr = row0 + r;
                tpf[ii] = make_float4(0.f, 0.f, 0.f, 0.f);
                if (gr < B)
                    tpf[ii] = reinterpret_cast<const float4*>(token)
                                  [(size_t)gr * (NE >> 2) + (kc + 1) * 16 + c4];
            }
#pragma unroll
            for (int ii = 0; ii < 4; ii++) {
                int i = tid + ii * 256;
                int m = i >> 4, k4 = i & 15;
                wpf[ii] = reinterpret_cast<const float4*>(whw)
                              [(size_t)m * (NE >> 2) + (kc + 1) * 16 + k4];
            }
        }
        // MMA on buffer p
        {
            uint32_t bufu = sb + (uint32_t)(p ? H1_BUF : 0);
#pragma unroll
            for (int kt = 0; kt < 4; kt++) {
                uint32_t aoff = (uint32_t)((((2 * kt + hi16) ^ low7)) << 4);
                uint32_t ah[4], al[4];
                lda4a(ah, bufu + HB_TOKHI + (uint32_t)(w * 2048) + Abase + aoff);
                lda4a(al, bufu + HB_TOKLO + (uint32_t)(w * 2048) + Abase + aoff);
#pragma unroll
                for (int nt = 0; nt < 8; nt++) {
                    uint32_t bh[2], bl[2];
                    ldb2(bh, bufu + HB_WHI, nt * 8, kt, lane);
                    ldb2(bl, bufu + HB_WLO, nt * 8, kt, lane);
                    mma_bf16(D[nt], ah, bh);
                    mma_bf16(D[nt], al, bh);
                    mma_bf16(D[nt], ah, bl);
                }
            }
        }
        // store next chunk into buffer 1-p
        if (kc + 1 < nch) {
            char* buf = smc + (p ? 0 : H1_BUF);
#pragma unroll
            for (int ii = 0; ii < 8; ii++) {
                int i = tid + ii * 256;
                int r = i >> 4, c4 = i & 15;
                float4 v = tpf[ii];
                float xh = bf_hi(v.x), yh = bf_hi(v.y), zh = bf_hi(v.z), wh = bf_hi(v.w);
                uint32_t off = swz(r, c4 * 4);
                *reinterpret_cast<uint2*>(buf + HB_TOKHI + off)
                    = make_uint2(pack_bf2(xh, yh), pack_bf2(zh, wh));
                *reinterpret_cast<uint2*>(buf + HB_TOKLO + off)
                    = make_uint2(pack_bf2(v.x - xh, v.y - yh), pack_bf2(v.z - zh, v.w - wh));
            }
#pragma unroll
            for (int ii = 0; ii < 4; ii++) {
                int i = tid + ii * 256;
                int m = i >> 4, k4 = i & 15;
                float4 v = wpf[ii];
                float xh = bf_hi(v.x), yh = bf_hi(v.y), zh = bf_hi(v.z), wh = bf_hi(v.w);
                uint32_t off = swz(m, k4 * 4);
                *reinterpret_cast<uint2*>(buf + HB_WHI + off)
                    = make_uint2(pack_bf2(xh, yh), pack_bf2(zh, wh));
                *reinterpret_cast<uint2*>(buf + HB_WLO + off)
                    = make_uint2(pack_bf2(v.x - xh, v.y - yh), pack_bf2(v.z - zh, v.w - wh));
            }
        }
        __syncthreads();
        p ^= 1;
    }

    // epilogue: rows r0 = w*16+g, r1 = r0+8; cols c = nt*8 + 2q + {0,1}
#pragma unroll
    for (int nt = 0; nt < 8; nt++) {
        int c = nt * 8 + 2 * q;
        float b0 = whb[c], b1 = whb[c + 1];
        int gr0 = row0 + w * 16 + g;
        int gr1 = gr0 + 8;
        if (gr0 < B)
            *reinterpret_cast<float2*>(&g_h0[(size_t)gr0 * 64 + c])
                = make_float2(D[nt][0] + b0, D[nt][1] + b1);
        if (gr1 < B)
            *reinterpret_cast<float2*>(&g_h0[(size_t)gr1 * 64 + c])
                = make_float2(D[nt][2] + b0, D[nt][3] + b1);
    }
}

// ============================================================================
// K2: GRU recurrence on warp-level HMMA. Epilogue constants live in REGISTERS
//   (one-time LDG gather), all epilogue smem addresses strength-reduced
//   (row&7 == g identity), D processed per m-tile. 2 blocks/SM.
// ============================================================================
#define XBUF  0
#define YPW   1024
#define A0HI  9216
#define A0LO  25600
#define A1HI  41984
#define A1LO  58368
#define BSTG  41984
#define K2_SMEM 74752

__global__ void __launch_bounds__(256, 2)
gru_mma(const float* __restrict__ wih,   // [192, 2]
        const float* __restrict__ whhg,  // [192, 64]
        const float* __restrict__ bihg,  // [192]
        const float* __restrict__ bhhg,  // [192]
        const float* __restrict__ wow,   // [2, 64]
        const float* __restrict__ wob,   // [2]
        float* __restrict__ out,         // [B, T, 2]
        int B, int T)
{
    extern __shared__ char smc[];
    const int tid  = threadIdx.x;
    const int w    = tid >> 5;
    const int lane = tid & 31;
    const int g    = lane >> 2;
    const int q    = lane & 3;
    const int c0   = 8 * w + 2 * q;       // this thread's first output col (per gate)
    const int row0 = blockIdx.x * 128;
    const uint32_t sb = s2u(smc);

    // zero x-buffer
    if (tid < 128)
        *reinterpret_cast<float2*>(smc + XBUF + tid * 8) = make_float2(0.f, 0.f);

    // one-time epilogue constants -> registers (cols c0, c0+1)
    const int cX = c0, cY = c0 + 1;
    const float Xwr0 = wih[cX * 2],         Xwr1 = wih[cX * 2 + 1];
    const float Xbr  = bihg[cX] + bhhg[cX];
    const float Xwz0 = wih[(64 + cX) * 2],  Xwz1 = wih[(64 + cX) * 2 + 1];
    const float Xbz  = bihg[64 + cX] + bhhg[64 + cX];
    const float Xwn0 = wih[(128 + cX) * 2], Xwn1 = wih[(128 + cX) * 2 + 1];
    const float Xbin = bihg[128 + cX],      Xbhn = bhhg[128 + cX];
    const float Xwo0 = wow[cX],             Xwo1 = wow[64 + cX];
    const float Ywr0 = wih[cY * 2],         Ywr1 = wih[cY * 2 + 1];
    const float Ybr  = bihg[cY] + bhhg[cY];
    const float Ywz0 = wih[(64 + cY) * 2],  Ywz1 = wih[(64 + cY) * 2 + 1];
    const float Ybz  = bihg[64 + cY] + bhhg[64 + cY];
    const float Ywn0 = wih[(128 + cY) * 2], Ywn1 = wih[(128 + cY) * 2 + 1];
    const float Ybin = bihg[128 + cY],      Ybhn = bhhg[128 + cY];
    const float Ywo0 = wow[cY],             Ywo1 = wow[64 + cY];
    const float ob0 = wob[0], ob1 = wob[1];

    // ---- phase 1: stage Whh HI into BSTG, load hi fragments ----
    for (int idx = tid; idx < G3 * 64; idx += 256) {
        int n = idx >> 6, k = idx & 63;
        float v = whhg[idx];
        *reinterpret_cast<unsigned short*>(smc + BSTG + swz(n, k))
            = __bfloat16_as_ushort(__float2bfloat16(bf_hi(v)));
    }
    __syncthreads();
    uint32_t Bh[3][4][2], Bl[3][4][2];
#pragma unroll
    for (int gi = 0; gi < 3; gi++)
#pragma unroll
        for (int kt = 0; kt < 4; kt++)
            ldb2(Bh[gi][kt], sb + BSTG, gi * 64 + 8 * w, kt, lane);
    __syncthreads();

    // ---- phase 2: stage Whh LO into BSTG; also stage h0 hi/lo into A0 ----
    for (int idx = tid; idx < G3 * 64; idx += 256) {
        int n = idx >> 6, k = idx & 63;
        float v = whhg[idx];
        *reinterpret_cast<unsigned short*>(smc + BSTG + swz(n, k))
            = __bfloat16_as_ushort(__float2bfloat16(v - bf_hi(v)));
    }
#pragma unroll
    for (int ii = 0; ii < 8; ii++) {
        int idx = tid + ii * 256;
        int r  = idx >> 4, c4 = idx & 15;
        int gr = row0 + r;
        float4 v = make_float4(0.f, 0.f, 0.f, 0.f);
        if (gr < B)
            v = reinterpret_cast<const float4*>(g_h0)[(size_t)gr * 16 + c4];
        float xh = bf_hi(v.x), yh = bf_hi(v.y), zh = bf_hi(v.z), wh = bf_hi(v.w);
        uint32_t off = swz(r, c4 * 4);
        *reinterpret_cast<uint2*>(smc + A0HI + off)
            = make_uint2(pack_bf2(xh, yh), pack_bf2(zh, wh));
        *reinterpret_cast<uint2*>(smc + A0LO + off)
            = make_uint2(pack_bf2(v.x - xh, v.y - yh), pack_bf2(v.z - zh, v.w - wh));
    }
    __syncthreads();
#pragma unroll
    for (int gi = 0; gi < 3; gi++)
#pragma unroll
        for (int kt = 0; kt < 4; kt++)
            ldb2(Bl[gi][kt], sb + BSTG, gi * 64 + 8 * w, kt, lane);
    __syncthreads();

    // strength-reduced addressing
    const uint32_t Abase = (uint32_t)((((lane & 7) | (lane & 8))) * 128);
    const int hi16 = lane >> 4;
    const int low7 = lane & 7;
    uint32_t aoff0 = (uint32_t)((((0 + hi16) ^ low7)) << 4);
    uint32_t aoff1 = (uint32_t)((((2 + hi16) ^ low7)) << 4);
    uint32_t aoff2 = (uint32_t)((((4 + hi16) ^ low7)) << 4);
    uint32_t aoff3 = (uint32_t)((((6 + hi16) ^ low7)) << 4);
    // epilogue offset: row&7 == g for all rows handled, so colpart is fixed
    const uint32_t colpart = (uint32_t)(((((c0 >> 3) ^ g)) << 4) + ((c0 & 7) << 1));
    const uint32_t epi_base = (uint32_t)(g * 128) + colpart;

    int p = 0;
#pragma unroll 1
    for (int step = 0; step < T; step++) {
        uint32_t rHI = sb + (uint32_t)(p ? A1HI : A0HI);
        uint32_t rLO = sb + (uint32_t)(p ? A1LO : A0LO);
        char* rHIc = smc + (p ? A1HI : A0HI);
        char* rLOc = smc + (p ? A1LO : A0LO);
        char* wHIc = smc + (p ? A0HI : A1HI);
        char* wLOc = smc + (p ? A0LO : A1LO);

#pragma unroll
        for (int mt = 0; mt < 8; mt++) {
            float D[3][4];
#pragma unroll
            for (int gi = 0; gi < 3; gi++)
#pragma unroll
                for (int e = 0; e < 4; e++) D[gi][e] = 0.f;

            const uint32_t mbase = (uint32_t)(mt * 2048) + Abase;
            uint32_t ah[4], al[4];
#pragma unroll
            for (int kt = 0; kt < 4; kt++) {
                uint32_t ao = (kt == 0) ? aoff0 : (kt == 1) ? aoff1 : (kt == 2) ? aoff2 : aoff3;
                lda4a(ah, rHI + mbase + ao);
                lda4a(al, rLO + mbase + ao);
#pragma unroll
                for (int gi = 0; gi < 3; gi++) {
                    mma_bf16(D[gi], ah, Bh[gi][kt]);
                    mma_bf16(D[gi], al, Bh[gi][kt]);
                    mma_bf16(D[gi], ah, Bl[gi][kt]);
                }
            }

            // epilogue for this m-tile
            int r0 = mt * 16 + g;
            int r1 = r0 + 8;
            float2 xA = *reinterpret_cast<const float2*>(smc + XBUF + r0 * 8);
            float2 xB = *reinterpret_cast<const float2*>(smc + XBUF + r1 * 8);
            uint32_t off0 = epi_base + (uint32_t)(mt * 2048);
            uint32_t off1 = off0 + 1024;
            float yv[4];
#pragma unroll
            for (int rowi = 0; rowi < 2; rowi++) {
                uint32_t offh = rowi ? off1 : off0;
                float xx0 = rowi ? xB.x : xA.x;
                float xx1 = rowi ? xB.y : xA.y;
                float2 hhi = bf22f(*reinterpret_cast<const uint32_t*>(rHIc + offh));
                float2 hlo = bf22f(*reinterpret_cast<const uint32_t*>(rLOc + offh));

                float dr0 = D[0][rowi * 2 + 0];
                float dz0 = D[1][rowi * 2 + 0];
                float dn0 = D[2][rowi * 2 + 0];
                float rg0 = sigf(fmaf(xx1, Xwr1, fmaf(xx0, Xwr0, Xbr)) + dr0);
                float ug0 = sigf(fmaf(xx1, Xwz1, fmaf(xx0, Xwz0, Xbz)) + dz0);
                float gn0 = fmaf(xx1, Xwn1, fmaf(xx0, Xwn0, Xbin));
                float ng0 = tanhfast(fmaf(rg0, dn0 + Xbhn, gn0));
                float hn0 = fmaf(ug0, (hhi.x + hlo.x) - ng0, ng0);

                float dr1 = D[0][rowi * 2 + 1];
                float dz1 = D[1][rowi * 2 + 1];
                float dn1 = D[2][rowi * 2 + 1];
                float rg1 = sigf(fmaf(xx1, Ywr1, fmaf(xx0, Ywr0, Ybr)) + dr1);
                float ug1 = sigf(fmaf(xx1, Ywz1, fmaf(xx0, Ywz0, Ybz)) + dz1);
                float gn1 = fmaf(xx1, Ywn1, fmaf(xx0, Ywn0, Ybin));
                float ng1 = tanhfast(fmaf(rg1, dn1 + Ybhn, gn1));
                float hn1 = fmaf(ug1, (hhi.y + hlo.y) - ng1, ng1);

                float h0h = bf_hi(hn0);
                float h1h = bf_hi(hn1);
                *reinterpret_cast<uint32_t*>(wHIc + offh) = pack_bf2(h0h, h1h);
                *reinterpret_cast<uint32_t*>(wLOc + offh)
                    = pack_bf2(hn0 - h0h, hn1 - h1h);
                yv[rowi * 2 + 0] = fmaf(hn1, Ywo0, hn0 * Xwo0);
                yv[rowi * 2 + 1] = fmaf(hn1, Ywo1, hn0 * Xwo1);
            }
            // sum over the 4 q-lanes (same rows) -> q==0 holds warp partial
#pragma unroll
            for (int d = 1; d < 4; d <<= 1)
#pragma unroll
                for (int u = 0; u < 4; u++)
                    yv[u] += __shfl_xor_sync(0xffffffffu, yv[u], d);
            if (q == 0) {
                *reinterpret_cast<float2*>(smc + YPW + (w * 128 + r0) * 8)
                    = make_float2(yv[0], yv[1]);
                *reinterpret_cast<float2*>(smc + YPW + (w * 128 + r1) * 8)
                    = make_float2(yv[2], yv[3]);
            }
        }
        __syncthreads();

        if (tid < 128) {
            int row = tid;
            float y0 = 0.f, y1 = 0.f;
#pragma unroll
            for (int ww = 0; ww < 8; ww++) {
                float2 pv = *reinterpret_cast<const float2*>(smc + YPW + (ww * 128 + row) * 8);
                y0 += pv.x;
                y1 += pv.y;
            }
            float2 xv = *reinterpret_cast<float2*>(smc + XBUF + row * 8);
            xv.x += y0 + ob0;
            xv.y += y1 + ob1;
            *reinterpret_cast<float2*>(smc + XBUF + row * 8) = xv;
            int grow = row0 + row;
            if (grow < B)
                *reinterpret_cast<float2*>(out + ((size_t)grow * T + step) * 2) = xv;
        }
        __syncthreads();
        p ^= 1;
    }
}

extern "C" void kernel_launch(void* const* d_in, const int* in_sizes, int n_in,
                              void* d_out, int out_size) {
    (void)n_in;
    const float* token = (const float*)d_in[0];
    const float* whw   = (const float*)d_in[1];
    const float* whb   = (const float*)d_in[2];
    const float* wih   = (const float*)d_in[3];
    const float* whh   = (const float*)d_in[4];
    const float* bih   = (const float*)d_in[5];
    const float* bhh   = (const float*)d_in[6];
    const float* wow   = (const float*)d_in[7];
    const float* wob   = (const float*)d_in[8];

    int NE = in_sizes[1] / HID;          // 1024
    int B  = in_sizes[0] / NE;           // 131072
    int T  = out_size / (B * 2);         // 10

    cudaFuncSetAttribute((const void*)head_tc,
                         cudaFuncAttributeMaxDynamicSharedMemorySize, H1_SMEM);
    cudaFuncSetAttribute((const void*)gru_mma,
                         cudaFuncAttributeMaxDynamicSharedMemorySize, K2_SMEM);

    int g1 = (B + 127) / 128;
    head_tc<<<g1, 256, H1_SMEM>>>(token, whw, whb, B, NE);

    int g2 = (B + 127) / 128;
    gru_mma<<<g2, 256, K2_SMEM>>>(wih, whh, bih, bhh, wow, wob,
                                  (float*)d_out, B, T);
}

// round 16
// speedup vs baseline: 3.0581x; 1.3873x over previous
#include <cuda_runtime.h>
#include <cuda_bf16.h>
#include <cuda_fp16.h>
#include <cstdint>
#include <cstddef>

#define HID 64
#define G3  192

typedef unsigned long long ull;

// scratch for h0 between the two kernels (B=131072 rows x 64)
__device__ float g_h0[131072ull * 64];

__device__ __forceinline__ float sigf(float v)  { return 1.0f / (1.0f + __expf(-v)); }
__device__ __forceinline__ float tanhfast(float v) {
    return 1.0f - 2.0f / (__expf(2.0f * v) + 1.0f);
}
__device__ __forceinline__ uint32_t s2u(const void* p) {
    uint32_t a;
    asm("{ .reg .u64 t; cvta.to.shared.u64 t, %1; cvt.u32.u64 %0, t; }" : "=r"(a) : "l"(p));
    return a;
}
__device__ __forceinline__ uint32_t swz(int row, int col) {   // row stride 128B, col in 2B units
    return (uint32_t)(row * 128 + (((col >> 3) ^ (row & 7)) << 4) + ((col & 7) << 1));
}
// pack two fp32 -> fp16x2 (a in low half, b in high half)
__device__ __forceinline__ uint32_t pack2h(float a, float b) {
    uint32_t r;
    asm("cvt.rn.f16x2.f32 %0, %1, %2;" : "=r"(r) : "f"(b), "f"(a));
    return r;
}
__device__ __forceinline__ float2 h22f(uint32_t u) {
    __half2 h = *reinterpret_cast<__half2*>(&u);
    return __half22float2(h);
}
// split (a,b) into fp16 hi word + fp16 residual word
__device__ __forceinline__ void split2h(float a, float b, uint32_t& hi, uint32_t& lo) {
    hi = pack2h(a, b);
    float2 f = h22f(hi);
    lo = pack2h(a - f.x, b - f.y);
}
__device__ __forceinline__ void lda4a(uint32_t* a, uint32_t addr) {
    asm volatile("ldmatrix.sync.aligned.m8n8.x4.shared.b16 {%0,%1,%2,%3}, [%4];"
        : "=r"(a[0]), "=r"(a[1]), "=r"(a[2]), "=r"(a[3]) : "r"(addr) : "memory");
}
__device__ __forceinline__ void ldb2(uint32_t* b, uint32_t base, int n0, int kt, int lane) {
    int row   = n0 + (lane & 7);
    int chunk = 2 * kt + ((lane >> 3) & 1);
    uint32_t addr = base + (uint32_t)(row * 128 + ((chunk ^ (row & 7)) << 4));
    asm volatile("ldmatrix.sync.aligned.m8n8.x2.shared.b16 {%0,%1}, [%2];"
        : "=r"(b[0]), "=r"(b[1]) : "r"(addr) : "memory");
}
// x4: loads B operands for TWO adjacent n-tiles (n0, n0+8) at k-tile kt
__device__ __forceinline__ void ldb4(uint32_t* b, uint32_t base, int n0, int kt, int lane) {
    int row   = n0 + (lane & 7) + ((lane & 16) >> 1);
    int chunk = 2 * kt + ((lane >> 3) & 1);
    uint32_t addr = base + (uint32_t)(row * 128 + ((chunk ^ (row & 7)) << 4));
    asm volatile("ldmatrix.sync.aligned.m8n8.x4.shared.b16 {%0,%1,%2,%3}, [%4];"
        : "=r"(b[0]), "=r"(b[1]), "=r"(b[2]), "=r"(b[3]) : "r"(addr) : "memory");
}
__device__ __forceinline__ void mma_f16(float* d, const uint32_t* a, const uint32_t* b) {
    asm("mma.sync.aligned.m16n8k16.row.col.f32.f16.f16.f32 "
        "{%0,%1,%2,%3}, {%4,%5,%6,%7}, {%8,%9}, {%0,%1,%2,%3};"
        : "+f"(d[0]), "+f"(d[1]), "+f"(d[2]), "+f"(d[3])
        : "r"(a[0]), "r"(a[1]), "r"(a[2]), "r"(a[3]), "r"(b[0]), "r"(b[1]));
}

// ============================================================================
// K1: h0 = token @ whw^T + whb  on fp16 HMMA (single pass), double-buffered.
// ============================================================================
#define HB_TOK   0
#define HB_W     16384
#define H1_BUF   24576
#define H1_SMEM  49152

__global__ void __launch_bounds__(256, 2)
head_tc(const float* __restrict__ token,
        const float* __restrict__ whw,
        const float* __restrict__ whb,
        int B, int NE)
{
    extern __shared__ char smc[];
    const uint32_t sb = s2u(smc);
    const int tid  = threadIdx.x;
    const int w    = tid >> 5;
    const int lane = tid & 31;
    const int g    = lane >> 2;
    const int q    = lane & 3;
    const int row0 = blockIdx.x * 128;

    const uint32_t Abase = (uint32_t)((((lane & 7) | (lane & 8))) * 128);
    const int hi16 = lane >> 4;
    const int low7 = lane & 7;

    float D[8][4];
#pragma unroll
    for (int nt = 0; nt < 8; nt++)
#pragma unroll
        for (int e = 0; e < 4; e++) D[nt][e] = 0.f;

    const int nch = NE >> 6;    // 16

    float4 tpf[8], wpf[4];
    // preload chunk 0
#pragma unroll
    for (int ii = 0; ii < 8; ii++) {
        int i = tid + ii * 256;
        int r = i >> 4, c4 = i & 15;
        int gr = row0 + r;
        tpf[ii] = make_float4(0.f, 0.f, 0.f, 0.f);
        if (gr < B)
            tpf[ii] = reinterpret_cast<const float4*>(token)[(size_t)gr * (NE >> 2) + c4];
    }
#pragma unroll
    for (int ii = 0; ii < 4; ii++) {
        int i = tid + ii * 256;
        int m = i >> 4, k4 = i & 15;
        wpf[ii] = reinterpret_cast<const float4*>(whw)[(size_t)m * (NE >> 2) + k4];
    }
    // store chunk 0 into buffer 0 (fp16 single)
    {
        char* buf = smc;
#pragma unroll
        for (int ii = 0; ii < 8; ii++) {
            int i = tid + ii * 256;
            int r = i >> 4, c4 = i & 15;
            float4 v = tpf[ii];
            *reinterpret_cast<uint2*>(buf + HB_TOK + swz(r, c4 * 4))
                = make_uint2(pack2h(v.x, v.y), pack2h(v.z, v.w));
        }
#pragma unroll
        for (int ii = 0; ii < 4; ii++) {
            int i = tid + ii * 256;
            int m = i >> 4, k4 = i & 15;
            float4 v = wpf[ii];
            *reinterpret_cast<uint2*>(buf + HB_W + swz(m, k4 * 4))
                = make_uint2(pack2h(v.x, v.y), pack2h(v.z, v.w));
        }
    }
    __syncthreads();

    int p = 0;
#pragma unroll 1
    for (int kc = 0; kc < nch; kc++) {
        // prefetch next chunk (LDG overlaps MMA)
        if (kc + 1 < nch) {
#pragma unroll
            for (int ii = 0; ii < 8; ii++) {
                int i = tid + ii * 256;
                int r = i >> 4, c4 = i & 15;
                int gr = row0 + r;
                tpf[ii] = make_float4(0.f, 0.f, 0.f, 0.f);
                if (gr < B)
                    tpf[ii] = reinterpret_cast<const float4*>(token)
                                  [(size_t)gr * (NE >> 2) + (kc + 1) * 16 + c4];
            }
#pragma unroll
            for (int ii = 0; ii < 4; ii++) {
                int i = tid + ii * 256;
                int m = i >> 4, k4 = i & 15;
                wpf[ii] = reinterpret_cast<const float4*>(whw)
                              [(size_t)m * (NE >> 2) + (kc + 1) * 16 + k4];
            }
        }
        // MMA on buffer p (fp16 single pass)
        {
            uint32_t bufu = sb + (uint32_t)(p ? H1_BUF : 0);
#pragma unroll
            for (int kt = 0; kt < 4; kt++) {
                uint32_t aoff = (uint32_t)((((2 * kt + hi16) ^ low7)) << 4);
                uint32_t a[4];
                lda4a(a, bufu + HB_TOK + (uint32_t)(w * 2048) + Abase + aoff);
#pragma unroll
                for (int ntp = 0; ntp < 4; ntp++) {
                    uint32_t bb[4];
                    ldb4(bb, bufu + HB_W, ntp * 16, kt, lane);
                    mma_f16(D[2 * ntp + 0], a, bb);
                    mma_f16(D[2 * ntp + 1], a, bb + 2);
                }
            }
        }
        // store next chunk into buffer 1-p
        if (kc + 1 < nch) {
            char* buf = smc + (p ? 0 : H1_BUF);
#pragma unroll
            for (int ii = 0; ii < 8; ii++) {
                int i = tid + ii * 256;
                int r = i >> 4, c4 = i & 15;
                float4 v = tpf[ii];
                *reinterpret_cast<uint2*>(buf + HB_TOK + swz(r, c4 * 4))
                    = make_uint2(pack2h(v.x, v.y), pack2h(v.z, v.w));
            }
#pragma unroll
            for (int ii = 0; ii < 4; ii++) {
                int i = tid + ii * 256;
                int m = i >> 4, k4 = i & 15;
                float4 v = wpf[ii];
                *reinterpret_cast<uint2*>(buf + HB_W + swz(m, k4 * 4))
                    = make_uint2(pack2h(v.x, v.y), pack2h(v.z, v.w));
            }
        }
        __syncthreads();
        p ^= 1;
    }

    // epilogue: rows r0 = w*16+g, r1 = r0+8; cols c = nt*8 + 2q + {0,1}
#pragma unroll
    for (int nt = 0; nt < 8; nt++) {
        int c = nt * 8 + 2 * q;
        float b0 = whb[c], b1 = whb[c + 1];
        int gr0 = row0 + w * 16 + g;
        int gr1 = gr0 + 8;
        if (gr0 < B)
            *reinterpret_cast<float2*>(&g_h0[(size_t)gr0 * 64 + c])
                = make_float2(D[nt][0] + b0, D[nt][1] + b1);
        if (gr1 < B)
            *reinterpret_cast<float2*>(&g_h0[(size_t)gr1 * 64 + c])
                = make_float2(D[nt][2] + b0, D[nt][3] + b1);
    }
}

// ============================================================================
// K2: GRU recurrence on fp16 HMMA, single pass. h stored as fp16 hi (MMA
//   operand) + fp16 residual (epilogue carry only -> recurrence carry stays
//   ~fp32-exact, quantization does not compound). Whh single fp16 in regs.
// ============================================================================
#define XBUF  0
#define YPW   1024
#define A0HI  9216
#define A0LO  25600
#define A1HI  41984
#define A1LO  58368
#define BSTG  41984
#define K2_SMEM 74752

__global__ void __launch_bounds__(256, 2)
gru_mma(const float* __restrict__ wih,   // [192, 2]
        const float* __restrict__ whhg,  // [192, 64]
        const float* __restrict__ bihg,  // [192]
        const float* __restrict__ bhhg,  // [192]
        const float* __restrict__ wow,   // [2, 64]
        const float* __restrict__ wob,   // [2]
        float* __restrict__ out,         // [B, T, 2]
        int B, int T)
{
    extern __shared__ char smc[];
    const int tid  = threadIdx.x;
    const int w    = tid >> 5;
    const int lane = tid & 31;
    const int g    = lane >> 2;
    const int q    = lane & 3;
    const int c0   = 8 * w + 2 * q;       // this thread's first output col (per gate)
    const int row0 = blockIdx.x * 128;
    const uint32_t sb = s2u(smc);

    // zero x-buffer
    if (tid < 128)
        *reinterpret_cast<float2*>(smc + XBUF + tid * 8) = make_float2(0.f, 0.f);

    // one-time epilogue constants -> registers (cols c0, c0+1)
    const int cX = c0, cY = c0 + 1;
    const float Xwr0 = wih[cX * 2],         Xwr1 = wih[cX * 2 + 1];
    const float Xbr  = bihg[cX] + bhhg[cX];
    const float Xwz0 = wih[(64 + cX) * 2],  Xwz1 = wih[(64 + cX) * 2 + 1];
    const float Xbz  = bihg[64 + cX] + bhhg[64 + cX];
    const float Xwn0 = wih[(128 + cX) * 2], Xwn1 = wih[(128 + cX) * 2 + 1];
    const float Xbin = bihg[128 + cX],      Xbhn = bhhg[128 + cX];
    const float Xwo0 = wow[cX],             Xwo1 = wow[64 + cX];
    const float Ywr0 = wih[cY * 2],         Ywr1 = wih[cY * 2 + 1];
    const float Ybr  = bihg[cY] + bhhg[cY];
    const float Ywz0 = wih[(64 + cY) * 2],  Ywz1 = wih[(64 + cY) * 2 + 1];
    const float Ybz  = bihg[64 + cY] + bhhg[64 + cY];
    const float Ywn0 = wih[(128 + cY) * 2], Ywn1 = wih[(128 + cY) * 2 + 1];
    const float Ybin = bihg[128 + cY],      Ybhn = bhhg[128 + cY];
    const float Ywo0 = wow[cY],             Ywo1 = wow[64 + cY];
    const float ob0 = wob[0], ob1 = wob[1];

    // ---- stage Whh (single fp16) into BSTG, load fragments ----
    for (int idx = tid; idx < G3 * 64; idx += 256) {
        int n = idx >> 6, k = idx & 63;
        *reinterpret_cast<unsigned short*>(smc + BSTG + swz(n, k))
            = __half_as_ushort(__float2half_rn(whhg[idx]));
    }
    __syncthreads();
    uint32_t Bw[3][4][2];
#pragma unroll
    for (int gi = 0; gi < 3; gi++)
#pragma unroll
        for (int kt = 0; kt < 4; kt++)
            ldb2(Bw[gi][kt], sb + BSTG, gi * 64 + 8 * w, kt, lane);
    __syncthreads();

    // ---- stage h0 (fp16 hi + residual) into A0 ----
#pragma unroll
    for (int ii = 0; ii < 8; ii++) {
        int idx = tid + ii * 256;
        int r  = idx >> 4, c4 = idx & 15;
        int gr = row0 + r;
        float4 v = make_float4(0.f, 0.f, 0.f, 0.f);
        if (gr < B)
            v = reinterpret_cast<const float4*>(g_h0)[(size_t)gr * 16 + c4];
        uint32_t h01, l01, h23, l23;
        split2h(v.x, v.y, h01, l01);
        split2h(v.z, v.w, h23, l23);
        uint32_t off = swz(r, c4 * 4);
        *reinterpret_cast<uint2*>(smc + A0HI + off) = make_uint2(h01, h23);
        *reinterpret_cast<uint2*>(smc + A0LO + off) = make_uint2(l01, l23);
    }
    __syncthreads();

    // strength-reduced addressing
    const uint32_t Abase = (uint32_t)((((lane & 7) | (lane & 8))) * 128);
    const int hi16 = lane >> 4;
    const int low7 = lane & 7;
    uint32_t aoff0 = (uint32_t)((((0 + hi16) ^ low7)) << 4);
    uint32_t aoff1 = (uint32_t)((((2 + hi16) ^ low7)) << 4);
    uint32_t aoff2 = (uint32_t)((((4 + hi16) ^ low7)) << 4);
    uint32_t aoff3 = (uint32_t)((((6 + hi16) ^ low7)) << 4);
    // epilogue offset: row&7 == g for all rows handled, so colpart is fixed
    const uint32_t colpart = (uint32_t)(((((c0 >> 3) ^ g)) << 4) + ((c0 & 7) << 1));
    const uint32_t epi_base = (uint32_t)(g * 128) + colpart;

    int p = 0;
#pragma unroll 1
    for (int step = 0; step < T; step++) {
        uint32_t rHI = sb + (uint32_t)(p ? A1HI : A0HI);
        char* rHIc = smc + (p ? A1HI : A0HI);
        char* rLOc = smc + (p ? A1LO : A0LO);
        char* wHIc = smc + (p ? A0HI : A1HI);
        char* wLOc = smc + (p ? A0LO : A1LO);

#pragma unroll
        for (int mt = 0; mt < 8; mt++) {
            float D[3][4];
#pragma unroll
            for (int gi = 0; gi < 3; gi++)
#pragma unroll
                for (int e = 0; e < 4; e++) D[gi][e] = 0.f;

            const uint32_t mbase = (uint32_t)(mt * 2048) + Abase;
#pragma unroll
            for (int kt = 0; kt < 4; kt++) {
                uint32_t ao = (kt == 0) ? aoff0 : (kt == 1) ? aoff1 : (kt == 2) ? aoff2 : aoff3;
                uint32_t a[4];
                lda4a(a, rHI + mbase + ao);
#pragma unroll
                for (int gi = 0; gi < 3; gi++)
                    mma_f16(D[gi], a, Bw[gi][kt]);
            }

            // epilogue for this m-tile
            int r0 = mt * 16 + g;
            int r1 = r0 + 8;
            float2 xA = *reinterpret_cast<const float2*>(smc + XBUF + r0 * 8);
            float2 xB = *reinterpret_cast<const float2*>(smc + XBUF + r1 * 8);
            uint32_t off0 = epi_base + (uint32_t)(mt * 2048);
            uint32_t off1 = off0 + 1024;
            float yv[4];
#pragma unroll
            for (int rowi = 0; rowi < 2; rowi++) {
                uint32_t offh = rowi ? off1 : off0;
                float xx0 = rowi ? xB.x : xA.x;
                float xx1 = rowi ? xB.y : xA.y;
                float2 hhi = h22f(*reinterpret_cast<const uint32_t*>(rHIc + offh));
                float2 hlo = h22f(*reinterpret_cast<const uint32_t*>(rLOc + offh));

                float dr0 = D[0][rowi * 2 + 0];
                float dz0 = D[1][rowi * 2 + 0];
                float dn0 = D[2][rowi * 2 + 0];
                float rg0 = sigf(fmaf(xx1, Xwr1, fmaf(xx0, Xwr0, Xbr)) + dr0);
                float ug0 = sigf(fmaf(xx1, Xwz1, fmaf(xx0, Xwz0, Xbz)) + dz0);
                float gn0 = fmaf(xx1, Xwn1, fmaf(xx0, Xwn0, Xbin));
                float ng0 = tanhfast(fmaf(rg0, dn0 + Xbhn, gn0));
                float hn0 = fmaf(ug0, (hhi.x + hlo.x) - ng0, ng0);

                float dr1 = D[0][rowi * 2 + 1];
                float dz1 = D[1][rowi * 2 + 1];
                float dn1 = D[2][rowi * 2 + 1];
                float rg1 = sigf(fmaf(xx1, Ywr1, fmaf(xx0, Ywr0, Ybr)) + dr1);
                float ug1 = sigf(fmaf(xx1, Ywz1, fmaf(xx0, Ywz0, Ybz)) + dz1);
                float gn1 = fmaf(xx1, Ywn1, fmaf(xx0, Ywn0, Ybin));
                float ng1 = tanhfast(fmaf(rg1, dn1 + Ybhn, gn1));
                float hn1 = fmaf(ug1, (hhi.y + hlo.y) - ng1, ng1);

                uint32_t hw, lw;
                split2h(hn0, hn1, hw, lw);
                *reinterpret_cast<uint32_t*>(wHIc + offh) = hw;
                *reinterpret_cast<uint32_t*>(wLOc + offh) = lw;
                yv[rowi * 2 + 0] = fmaf(hn1, Ywo0, hn0 * Xwo0);
                yv[rowi * 2 + 1] = fmaf(hn1, Ywo1, hn0 * Xwo1);
            }
            // sum over the 4 q-lanes (same rows) -> q==0 holds warp partial
#pragma unroll
            for (int d = 1; d < 4; d <<= 1)
#pragma unroll
                for (int u = 0; u < 4; u++)
                    yv[u] += __shfl_xor_sync(0xffffffffu, yv[u], d);
            if (q == 0) {
                *reinterpret_cast<float2*>(smc + YPW + (w * 128 + r0) * 8)
                    = make_float2(yv[0], yv[1]);
                *reinterpret_cast<float2*>(smc + YPW + (w * 128 + r1) * 8)
                    = make_float2(yv[2], yv[3]);
            }
        }
        __syncthreads();

        if (tid < 128) {
            int row = tid;
            float y0 = 0.f, y1 = 0.f;
#pragma unroll
            for (int ww = 0; ww < 8; ww++) {
                float2 pv = *reinterpret_cast<const float2*>(smc + YPW + (ww * 128 + row) * 8);
                y0 += pv.x;
                y1 += pv.y;
            }
            float2 xv = *reinterpret_cast<float2*>(smc + XBUF + row * 8);
            xv.x += y0 + ob0;
            xv.y += y1 + ob1;
            *reinterpret_cast<float2*>(smc + XBUF + row * 8) = xv;
            int grow = row0 + row;
            if (grow < B)
                *reinterpret_cast<float2*>(out + ((size_t)grow * T + step) * 2) = xv;
        }
        __syncthreads();
        p ^= 1;
    }
}

extern "C" void kernel_launch(void* const* d_in, const int* in_sizes, int n_in,
                              void* d_out, int out_size) {
    (void)n_in;
    const float* token = (const float*)d_in[0];
    const float* whw   = (const float*)d_in[1];
    const float* whb   = (const float*)d_in[2];
    const float* wih   = (const float*)d_in[3];
    const float* whh   = (const float*)d_in[4];
    const float* bih   = (const float*)d_in[5];
    const float* bhh   = (const float*)d_in[6];
    const float* wow   = (const float*)d_in[7];
    const float* wob   = (const float*)d_in[8];

    int NE = in_sizes[1] / HID;          // 1024
    int B  = in_sizes[0] / NE;           // 131072
    int T  = out_size / (B * 2);         // 10

    cudaFuncSetAttribute((const void*)head_tc,
                         cudaFuncAttributeMaxDynamicSharedMemorySize, H1_SMEM);
    cudaFuncSetAttribute((const void*)gru_mma,
                         cudaFuncAttributeMaxDynamicSharedMemorySize, K2_SMEM);

    int g1 = (B + 127) / 128;
    head_tc<<<g1, 256, H1_SMEM>>>(token, whw, whb, B, NE);

    int g2 = (B + 127) / 128;
    gru_mma<<<g2, 256, K2_SMEM>>>(wih, whh, bih, bhh, wow, wob,
                                  (float*)d_out, B, T);
}

// round 17
// speedup vs baseline: 4.2938x; 1.4041x over previous
#include <cuda_runtime.h>
#include <cuda_bf16.h>
#include <cuda_fp16.h>
#include <cstdint>
#include <cstddef>

#define HID 64
#define G3  192

typedef unsigned long long ull;

// scratch for h0 between the two kernels (B=131072 rows x 64)
__device__ float g_h0[131072ull * 64];

__device__ __forceinline__ float tanh_ap(float v) {
    float r;
    asm("tanh.approx.f32 %0, %1;" : "=f"(r) : "f"(v));
    return r;
}
__device__ __forceinline__ uint32_t s2u(const void* p) {
    uint32_t a;
    asm("{ .reg .u64 t; cvta.to.shared.u64 t, %1; cvt.u32.u64 %0, t; }" : "=r"(a) : "l"(p));
    return a;
}
__device__ __forceinline__ uint32_t swz(int row, int col) {   // row stride 128B, col in 2B units
    return (uint32_t)(row * 128 + (((col >> 3) ^ (row & 7)) << 4) + ((col & 7) << 1));
}
// pack two fp32 -> fp16x2 (a in low half, b in high half)
__device__ __forceinline__ uint32_t pack2h(float a, float b) {
    uint32_t r;
    asm("cvt.rn.f16x2.f32 %0, %1, %2;" : "=r"(r) : "f"(b), "f"(a));
    return r;
}
__device__ __forceinline__ float2 h22f(uint32_t u) {
    __half2 h = *reinterpret_cast<__half2*>(&u);
    return __half22float2(h);
}
// split (a,b) into fp16 hi word + fp16 residual word
__device__ __forceinline__ void split2h(float a, float b, uint32_t& hi, uint32_t& lo) {
    hi = pack2h(a, b);
    float2 f = h22f(hi);
    lo = pack2h(a - f.x, b - f.y);
}
__device__ __forceinline__ void lda4a(uint32_t* a, uint32_t addr) {
    asm volatile("ldmatrix.sync.aligned.m8n8.x4.shared.b16 {%0,%1,%2,%3}, [%4];"
        : "=r"(a[0]), "=r"(a[1]), "=r"(a[2]), "=r"(a[3]) : "r"(addr) : "memory");
}
__device__ __forceinline__ void ldb2(uint32_t* b, uint32_t base, int n0, int kt, int lane) {
    int row   = n0 + (lane & 7);
    int chunk = 2 * kt + ((lane >> 3) & 1);
    uint32_t addr = base + (uint32_t)(row * 128 + ((chunk ^ (row & 7)) << 4));
    asm volatile("ldmatrix.sync.aligned.m8n8.x2.shared.b16 {%0,%1}, [%2];"
        : "=r"(b[0]), "=r"(b[1]) : "r"(addr) : "memory");
}
// x4: loads B operands for TWO adjacent n-tiles (n0, n0+8) at k-tile kt
__device__ __forceinline__ void ldb4(uint32_t* b, uint32_t base, int n0, int kt, int lane) {
    int row   = n0 + (lane & 7) + ((lane & 16) >> 1);
    int chunk = 2 * kt + ((lane >> 3) & 1);
    uint32_t addr = base + (uint32_t)(row * 128 + ((chunk ^ (row & 7)) << 4));
    asm volatile("ldmatrix.sync.aligned.m8n8.x4.shared.b16 {%0,%1,%2,%3}, [%4];"
        : "=r"(b[0]), "=r"(b[1]), "=r"(b[2]), "=r"(b[3]) : "r"(addr) : "memory");
}
__device__ __forceinline__ void mma_f16(float* d, const uint32_t* a, const uint32_t* b) {
    asm("mma.sync.aligned.m16n8k16.row.col.f32.f16.f16.f32 "
        "{%0,%1,%2,%3}, {%4,%5,%6,%7}, {%8,%9}, {%0,%1,%2,%3};"
        : "+f"(d[0]), "+f"(d[1]), "+f"(d[2]), "+f"(d[3])
        : "r"(a[0]), "r"(a[1]), "r"(a[2]), "r"(a[3]), "r"(b[0]), "r"(b[1]));
}

// ============================================================================
// K1: h0 = token @ whw^T + whb  on fp16 HMMA, 2-pass (W = hi + residual),
//     double-buffered.
// ============================================================================
#define HB_TOK   0
#define HB_W     16384
#define HB_WLO   24576
#define H1_BUF   32768
#define H1_SMEM  65536

__global__ void __launch_bounds__(256, 2)
head_tc(const float* __restrict__ token,
        const float* __restrict__ whw,
        const float* __restrict__ whb,
        int B, int NE)
{
    extern __shared__ char smc[];
    const uint32_t sb = s2u(smc);
    const int tid  = threadIdx.x;
    const int w    = tid >> 5;
    const int lane = tid & 31;
    const int g    = lane >> 2;
    const int q    = lane & 3;
    const int row0 = blockIdx.x * 128;

    const uint32_t Abase = (uint32_t)((((lane & 7) | (lane & 8))) * 128);
    const int hi16 = lane >> 4;
    const int low7 = lane & 7;

    float D[8][4];
#pragma unroll
    for (int nt = 0; nt < 8; nt++)
#pragma unroll
        for (int e = 0; e < 4; e++) D[nt][e] = 0.f;

    const int nch = NE >> 6;    // 16

    float4 tpf[8], wpf[4];
    // preload chunk 0
#pragma unroll
    for (int ii = 0; ii < 8; ii++) {
        int i = tid + ii * 256;
        int r = i >> 4, c4 = i & 15;
        int gr = row0 + r;
        tpf[ii] = make_float4(0.f, 0.f, 0.f, 0.f);
        if (gr < B)
            tpf[ii] = reinterpret_cast<const float4*>(token)[(size_t)gr * (NE >> 2) + c4];
    }
#pragma unroll
    for (int ii = 0; ii < 4; ii++) {
        int i = tid + ii * 256;
        int m = i >> 4, k4 = i & 15;
        wpf[ii] = reinterpret_cast<const float4*>(whw)[(size_t)m * (NE >> 2) + k4];
    }
    // store chunk 0 into buffer 0
    {
        char* buf = smc;
#pragma unroll
        for (int ii = 0; ii < 8; ii++) {
            int i = tid + ii * 256;
            int r = i >> 4, c4 = i & 15;
            float4 v = tpf[ii];
            *reinterpret_cast<uint2*>(buf + HB_TOK + swz(r, c4 * 4))
                = make_uint2(pack2h(v.x, v.y), pack2h(v.z, v.w));
        }
#pragma unroll
        for (int ii = 0; ii < 4; ii++) {
            int i = tid + ii * 256;
            int m = i >> 4, k4 = i & 15;
            float4 v = wpf[ii];
            uint32_t h01, l01, h23, l23;
            split2h(v.x, v.y, h01, l01);
            split2h(v.z, v.w, h23, l23);
            uint32_t off = swz(m, k4 * 4);
            *reinterpret_cast<uint2*>(buf + HB_W + off)   = make_uint2(h01, h23);
            *reinterpret_cast<uint2*>(buf + HB_WLO + off) = make_uint2(l01, l23);
        }
    }
    __syncthreads();

    int p = 0;
#pragma unroll 1
    for (int kc = 0; kc < nch; kc++) {
        // prefetch next chunk (LDG overlaps MMA)
        if (kc + 1 < nch) {
#pragma unroll
            for (int ii = 0; ii < 8; ii++) {
                int i = tid + ii * 256;
                int r = i >> 4, c4 = i & 15;
                int gr = row0 + r;
                tpf[ii] = make_float4(0.f, 0.f, 0.f, 0.f);
                if (gr < B)
                    tpf[ii] = reinterpret_cast<const float4*>(token)
                                  [(size_t)gr * (NE >> 2) + (kc + 1) * 16 + c4];
            }
#pragma unroll
            for (int ii = 0; ii < 4; ii++) {
                int i = tid + ii * 256;
                int m = i >> 4, k4 = i & 15;
                wpf[ii] = reinterpret_cast<const float4*>(whw)
                              [(size_t)m * (NE >> 2) + (kc + 1) * 16 + k4];
            }
        }
        // MMA on buffer p (2-pass: W hi + W lo)
        {
            uint32_t bufu = sb + (uint32_t)(p ? H1_BUF : 0);
#pragma unroll
            for (int kt = 0; kt < 4; kt++) {
                uint32_t aoff = (uint32_t)((((2 * kt + hi16) ^ low7)) << 4);
                uint32_t a[4];
                lda4a(a, bufu + HB_TOK + (uint32_t)(w * 2048) + Abase + aoff);
#pragma unroll
                for (int ntp = 0; ntp < 4; ntp++) {
                    uint32_t bh[4], bl[4];
                    ldb4(bh, bufu + HB_W, ntp * 16, kt, lane);
                    ldb4(bl, bufu + HB_WLO, ntp * 16, kt, lane);
                    mma_f16(D[2 * ntp + 0], a, bh);
                    mma_f16(D[2 * ntp + 1], a, bh + 2);
                    mma_f16(D[2 * ntp + 0], a, bl);
                    mma_f16(D[2 * ntp + 1], a, bl + 2);
                }
            }
        }
        // store next chunk into buffer 1-p
        if (kc + 1 < nch) {
            char* buf = smc + (p ? 0 : H1_BUF);
#pragma unroll
            for (int ii = 0; ii < 8; ii++) {
                int i = tid + ii * 256;
                int r = i >> 4, c4 = i & 15;
                float4 v = tpf[ii];
                *reinterpret_cast<uint2*>(buf + HB_TOK + swz(r, c4 * 4))
                    = make_uint2(pack2h(v.x, v.y), pack2h(v.z, v.w));
            }
#pragma unroll
            for (int ii = 0; ii < 4; ii++) {
                int i = tid + ii * 256;
                int m = i >> 4, k4 = i & 15;
                float4 v = wpf[ii];
                uint32_t h01, l01, h23, l23;
                split2h(v.x, v.y, h01, l01);
                split2h(v.z, v.w, h23, l23);
                uint32_t off = swz(m, k4 * 4);
                *reinterpret_cast<uint2*>(buf + HB_W + off)   = make_uint2(h01, h23);
                *reinterpret_cast<uint2*>(buf + HB_WLO + off) = make_uint2(l01, l23);
            }
        }
        __syncthreads();
        p ^= 1;
    }

    // epilogue: rows r0 = w*16+g, r1 = r0+8; cols c = nt*8 + 2q + {0,1}
#pragma unroll
    for (int nt = 0; nt < 8; nt++) {
        int c = nt * 8 + 2 * q;
        float b0 = whb[c], b1 = whb[c + 1];
        int gr0 = row0 + w * 16 + g;
        int gr1 = gr0 + 8;
        if (gr0 < B)
            *reinterpret_cast<float2*>(&g_h0[(size_t)gr0 * 64 + c])
                = make_float2(D[nt][0] + b0, D[nt][1] + b1);
        if (gr1 < B)
            *reinterpret_cast<float2*>(&g_h0[(size_t)gr1 * 64 + c])
                = make_float2(D[nt][2] + b0, D[nt][3] + b1);
    }
}

// ============================================================================
// K2: GRU on fp16 HMMA, 2-pass (Whh = hi + residual, exact weights). h stored
//   fp16 hi (MMA) + residual (epilogue carry). r/z weight rows and x/bias
//   constants pre-scaled by 0.5 so sigmoid = 0.5 + 0.5*tanh(pre) via MUFU.TANH
//   (3 MUFU/element instead of 6).
// ============================================================================
#define XBUF  0
#define YPW   1024
#define A0HI  9216
#define A0LO  25600
#define A1HI  41984
#define A1LO  58368
#define BSTG  41984
#define K2_SMEM 74752

__global__ void __launch_bounds__(256, 2)
gru_mma(const float* __restrict__ wih,   // [192, 2]
        const float* __restrict__ whhg,  // [192, 64]
        const float* __restrict__ bihg,  // [192]
        const float* __restrict__ bhhg,  // [192]
        const float* __restrict__ wow,   // [2, 64]
        const float* __restrict__ wob,   // [2]
        float* __restrict__ out,         // [B, T, 2]
        int B, int T)
{
    extern __shared__ char smc[];
    const int tid  = threadIdx.x;
    const int w    = tid >> 5;
    const int lane = tid & 31;
    const int g    = lane >> 2;
    const int q    = lane & 3;
    const int c0   = 8 * w + 2 * q;       // this thread's first output col (per gate)
    const int row0 = blockIdx.x * 128;
    const uint32_t sb = s2u(smc);

    // zero x-buffer
    if (tid < 128)
        *reinterpret_cast<float2*>(smc + XBUF + tid * 8) = make_float2(0.f, 0.f);

    // one-time epilogue constants -> registers (cols c0, c0+1); r/z pre-halved
    const int cX = c0, cY = c0 + 1;
    const float Xwr0 = 0.5f * wih[cX * 2],         Xwr1 = 0.5f * wih[cX * 2 + 1];
    const float Xbr  = 0.5f * (bihg[cX] + bhhg[cX]);
    const float Xwz0 = 0.5f * wih[(64 + cX) * 2],  Xwz1 = 0.5f * wih[(64 + cX) * 2 + 1];
    const float Xbz  = 0.5f * (bihg[64 + cX] + bhhg[64 + cX]);
    const float Xwn0 = wih[(128 + cX) * 2],        Xwn1 = wih[(128 + cX) * 2 + 1];
    const float Xbin = bihg[128 + cX],             Xbhn = bhhg[128 + cX];
    const float Xwo0 = wow[cX],                    Xwo1 = wow[64 + cX];
    const float Ywr0 = 0.5f * wih[cY * 2],         Ywr1 = 0.5f * wih[cY * 2 + 1];
    const float Ybr  = 0.5f * (bihg[cY] + bhhg[cY]);
    const float Ywz0 = 0.5f * wih[(64 + cY) * 2],  Ywz1 = 0.5f * wih[(64 + cY) * 2 + 1];
    const float Ybz  = 0.5f * (bihg[64 + cY] + bhhg[64 + cY]);
    const float Ywn0 = wih[(128 + cY) * 2],        Ywn1 = wih[(128 + cY) * 2 + 1];
    const float Ybin = bihg[128 + cY],             Ybhn = bhhg[128 + cY];
    const float Ywo0 = wow[cY],                    Ywo1 = wow[64 + cY];
    const float ob0 = wob[0], ob1 = wob[1];

    // ---- phase 1: stage Whh HI (r/z rows pre-scaled by 0.5) into BSTG ----
    for (int idx = tid; idx < G3 * 64; idx += 256) {
        int n = idx >> 6, k = idx & 63;
        float v = whhg[idx];
        if (n < 128) v *= 0.5f;
        *reinterpret_cast<unsigned short*>(smc + BSTG + swz(n, k))
            = __half_as_ushort(__float2half_rn(v));
    }
    __syncthreads();
    uint32_t Bh[3][4][2], Bl[3][4][2];
#pragma unroll
    for (int gi = 0; gi < 3; gi++)
#pragma unroll
        for (int kt = 0; kt < 4; kt++)
            ldb2(Bh[gi][kt], sb + BSTG, gi * 64 + 8 * w, kt, lane);
    __syncthreads();

    // ---- phase 2: stage Whh LO (residual of the scaled value) ----
    for (int idx = tid; idx < G3 * 64; idx += 256) {
        int n = idx >> 6, k = idx & 63;
        float v = whhg[idx];
        if (n < 128) v *= 0.5f;
        float vh = __half2float(__float2half_rn(v));
        *reinterpret_cast<unsigned short*>(smc + BSTG + swz(n, k))
            = __half_as_ushort(__float2half_rn(v - vh));
    }
    // stage h0 (fp16 hi + residual) into A0
#pragma unroll
    for (int ii = 0; ii < 8; ii++) {
        int idx = tid + ii * 256;
        int r  = idx >> 4, c4 = idx & 15;
        int gr = row0 + r;
        float4 v = make_float4(0.f, 0.f, 0.f, 0.f);
        if (gr < B)
            v = reinterpret_cast<const float4*>(g_h0)[(size_t)gr * 16 + c4];
        uint32_t h01, l01, h23, l23;
        split2h(v.x, v.y, h01, l01);
        split2h(v.z, v.w, h23, l23);
        uint32_t off = swz(r, c4 * 4);
        *reinterpret_cast<uint2*>(smc + A0HI + off) = make_uint2(h01, h23);
        *reinterpret_cast<uint2*>(smc + A0LO + off) = make_uint2(l01, l23);
    }
    __syncthreads();
#pragma unroll
    for (int gi = 0; gi < 3; gi++)
#pragma unroll
        for (int kt = 0; kt < 4; kt++)
            ldb2(Bl[gi][kt], sb + BSTG, gi * 64 + 8 * w, kt, lane);
    __syncthreads();

    // strength-reduced addressing
    const uint32_t Abase = (uint32_t)((((lane & 7) | (lane & 8))) * 128);
    const int hi16 = lane >> 4;
    const int low7 = lane & 7;
    uint32_t aoff0 = (uint32_t)((((0 + hi16) ^ low7)) << 4);
    uint32_t aoff1 = (uint32_t)((((2 + hi16) ^ low7)) << 4);
    uint32_t aoff2 = (uint32_t)((((4 + hi16) ^ low7)) << 4);
    uint32_t aoff3 = (uint32_t)((((6 + hi16) ^ low7)) << 4);
    const uint32_t colpart = (uint32_t)(((((c0 >> 3) ^ g)) << 4) + ((c0 & 7) << 1));
    const uint32_t epi_base = (uint32_t)(g * 128) + colpart;

    int p = 0;
#pragma unroll 1
    for (int step = 0; step < T; step++) {
        uint32_t rHI = sb + (uint32_t)(p ? A1HI : A0HI);
        char* rHIc = smc + (p ? A1HI : A0HI);
        char* rLOc = smc + (p ? A1LO : A0LO);
        char* wHIc = smc + (p ? A0HI : A1HI);
        char* wLOc = smc + (p ? A0LO : A1LO);

#pragma unroll
        for (int mt = 0; mt < 8; mt++) {
            float D[3][4];
#pragma unroll
            for (int gi = 0; gi < 3; gi++)
#pragma unroll
                for (int e = 0; e < 4; e++) D[gi][e] = 0.f;

            const uint32_t mbase = (uint32_t)(mt * 2048) + Abase;
#pragma unroll
            for (int kt = 0; kt < 4; kt++) {
                uint32_t ao = (kt == 0) ? aoff0 : (kt == 1) ? aoff1 : (kt == 2) ? aoff2 : aoff3;
                uint32_t a[4];
                lda4a(a, rHI + mbase + ao);
#pragma unroll
                for (int gi = 0; gi < 3; gi++) {
                    mma_f16(D[gi], a, Bh[gi][kt]);
                    mma_f16(D[gi], a, Bl[gi][kt]);
                }
            }

            // epilogue for this m-tile
            int r0 = mt * 16 + g;
            int r1 = r0 + 8;
            float2 xA = *reinterpret_cast<const float2*>(smc + XBUF + r0 * 8);
            float2 xB = *reinterpret_cast<const float2*>(smc + XBUF + r1 * 8);
            uint32_t off0 = epi_base + (uint32_t)(mt * 2048);
            uint32_t off1 = off0 + 1024;
            float yv[4];
#pragma unroll
            for (int rowi = 0; rowi < 2; rowi++) {
                uint32_t offh = rowi ? off1 : off0;
                float xx0 = rowi ? xB.x : xA.x;
                float xx1 = rowi ? xB.y : xA.y;
                float2 hhi = h22f(*reinterpret_cast<const uint32_t*>(rHIc + offh));
                float2 hlo = h22f(*reinterpret_cast<const uint32_t*>(rLOc + offh));

                float dr0 = D[0][rowi * 2 + 0];
                float dz0 = D[1][rowi * 2 + 0];
                float dn0 = D[2][rowi * 2 + 0];
                float rg0 = fmaf(0.5f, tanh_ap(fmaf(xx1, Xwr1, fmaf(xx0, Xwr0, Xbr)) + dr0), 0.5f);
                float ug0 = fmaf(0.5f, tanh_ap(fmaf(xx1, Xwz1, fmaf(xx0, Xwz0, Xbz)) + dz0), 0.5f);
                float gn0 = fmaf(xx1, Xwn1, fmaf(xx0, Xwn0, Xbin));
                float ng0 = tanh_ap(fmaf(rg0, dn0 + Xbhn, gn0));
                float hn0 = fmaf(ug0, (hhi.x + hlo.x) - ng0, ng0);

                float dr1 = D[0][rowi * 2 + 1];
                float dz1 = D[1][rowi * 2 + 1];
                float dn1 = D[2][rowi * 2 + 1];
                float rg1 = fmaf(0.5f, tanh_ap(fmaf(xx1, Ywr1, fmaf(xx0, Ywr0, Ybr)) + dr1), 0.5f);
                float ug1 = fmaf(0.5f, tanh_ap(fmaf(xx1, Ywz1, fmaf(xx0, Ywz0, Ybz)) + dz1), 0.5f);
                float gn1 = fmaf(xx1, Ywn1, fmaf(xx0, Ywn0, Ybin));
                float ng1 = tanh_ap(fmaf(rg1, dn1 + Ybhn, gn1));
                float hn1 = fmaf(ug1, (hhi.y + hlo.y) - ng1, ng1);

                uint32_t hw, lw;
                split2h(hn0, hn1, hw, lw);
                *reinterpret_cast<uint32_t*>(wHIc + offh) = hw;
                *reinterpret_cast<uint32_t*>(wLOc + offh) = lw;
                yv[rowi * 2 + 0] = fmaf(hn1, Ywo0, hn0 * Xwo0);
                yv[rowi * 2 + 1] = fmaf(hn1, Ywo1, hn0 * Xwo1);
            }
            // sum over the 4 q-lanes (same rows) -> q==0 holds warp partial
#pragma unroll
            for (int d = 1; d < 4; d <<= 1)
#pragma unroll
                for (int u = 0; u < 4; u++)
                    yv[u] += __shfl_xor_sync(0xffffffffu, yv[u], d);
            if (q == 0) {
                *reinterpret_cast<float2*>(smc + YPW + (w * 128 + r0) * 8)
                    = make_float2(yv[0], yv[1]);
                *reinterpret_cast<float2*>(smc + YPW + (w * 128 + r1) * 8)
                    = make_float2(yv[2], yv[3]);
            }
        }
        __syncthreads();

        if (tid < 128) {
            int row = tid;
            float y0 = 0.f, y1 = 0.f;
#pragma unroll
            for (int ww = 0; ww < 8; ww++) {
                float2 pv = *reinterpret_cast<const float2*>(smc + YPW + (ww * 128 + row) * 8);
                y0 += pv.x;
                y1 += pv.y;
            }
            float2 xv = *reinterpret_cast<float2*>(smc + XBUF + row * 8);
            xv.x += y0 + ob0;
            xv.y += y1 + ob1;
            *reinterpret_cast<float2*>(smc + XBUF + row * 8) = xv;
            int grow = row0 + row;
            if (grow < B)
                *reinterpret_cast<float2*>(out + ((size_t)grow * T + step) * 2) = xv;
        }
        __syncthreads();
        p ^= 1;
    }
}

extern "C" void kernel_launch(void* const* d_in, const int* in_sizes, int n_in,
                              void* d_out, int out_size) {
    (void)n_in;
    const float* token = (const float*)d_in[0];
    const float* whw   = (const float*)d_in[1];
    const float* whb   = (const float*)d_in[2];
    const float* wih   = (const float*)d_in[3];
    const float* whh   = (const float*)d_in[4];
    const float* bih   = (const float*)d_in[5];
    const float* bhh   = (const float*)d_in[6];
    const float* wow   = (const float*)d_in[7];
    const float* wob   = (const float*)d_in[8];

    int NE = in_sizes[1] / HID;          // 1024
    int B  = in_sizes[0] / NE;           // 131072
    int T  = out_size / (B * 2);         // 10

    cudaFuncSetAttribute((const void*)head_tc,
                         cudaFuncAttributeMaxDynamicSharedMemorySize, H1_SMEM);
    cudaFuncSetAttribute((const void*)gru_mma,
                         cudaFuncAttributeMaxDynamicSharedMemorySize, K2_SMEM);

    int g1 = (B + 127) / 128;
    head_tc<<<g1, 256, H1_SMEM>>>(token, whw, whb, B, NE);

    int g2 = (B + 127) / 128;
    gru_mma<<<g2, 256, K2_SMEM>>>(wih, whh, bih, bhh, wow, wob,
                                  (float*)d_out, B, T);
}